// round 1
// baseline (speedup 1.0000x reference)
#include <cuda_runtime.h>
#include <math.h>

// ---------------- problem constants ----------------
constexpr int LL   = 4608;
constexpr int HIDC = 3072;
constexpr int NHC  = 24;
constexpr int HDC  = 128;
constexpr int MLPC = 12288;
constexpr int RK   = 32;
constexpr int D3H  = 3 * HIDC;          // 9216
constexpr int NQKV = 3 * HIDC + MLPC;   // 21504
constexpr int NCAT = HIDC + MLPC;       // 15360

// ---------------- scratch (device globals; no allocation allowed) ----------------
__device__ float g_mod[D3H];                       // shift|scale|gate
__device__ float g_xmod[(size_t)LL * HIDC];        // 56.6 MB
__device__ float g_qkv[(size_t)LL * NQKV];         // 396 MB
__device__ float g_y[(size_t)LL * NCAT];           // 283 MB  (attn | gelu(mlp))
__device__ float g_t1[LL * RK];
__device__ float g_t2[LL * RK];

// ---------------- K1: mod = silu(vec) @ mod_w^T + mod_b (warp per output) ----------------
__global__ __launch_bounds__(256) void k_mod(const float* __restrict__ vec,
                                             const float* __restrict__ mod_w,
                                             const float* __restrict__ mod_b) {
    int j = blockIdx.x * 8 + (threadIdx.x >> 5);
    int lane = threadIdx.x & 31;
    if (j >= D3H) return;
    const float* wr = mod_w + (size_t)j * HIDC;
    float acc = 0.f;
    for (int k = lane; k < HIDC; k += 32) {
        float s = vec[k];
        float si = s / (1.f + expf(-s));
        acc += si * wr[k];
    }
    #pragma unroll
    for (int o = 16; o; o >>= 1) acc += __shfl_xor_sync(0xffffffffu, acc, o);
    if (lane == 0) g_mod[j] = acc + mod_b[j];
}

// ---------------- K2: LayerNorm + modulation -> g_xmod ----------------
__global__ __launch_bounds__(256) void k_ln(const float* __restrict__ x) {
    __shared__ float rs[8], rs2[8];
    int m = blockIdx.x;
    const float* row = x + (size_t)m * HIDC;
    float v[12];
    float s = 0.f, s2 = 0.f;
    #pragma unroll
    for (int i = 0; i < 12; i++) {
        v[i] = row[threadIdx.x + i * 256];
        s += v[i]; s2 += v[i] * v[i];
    }
    int lane = threadIdx.x & 31, w = threadIdx.x >> 5;
    #pragma unroll
    for (int o = 16; o; o >>= 1) {
        s  += __shfl_xor_sync(0xffffffffu, s, o);
        s2 += __shfl_xor_sync(0xffffffffu, s2, o);
    }
    if (!lane) { rs[w] = s; rs2[w] = s2; }
    __syncthreads();
    float S = 0.f, S2 = 0.f;
    #pragma unroll
    for (int i = 0; i < 8; i++) { S += rs[i]; S2 += rs2[i]; }
    float mu = S * (1.f / HIDC);
    float var = S2 * (1.f / HIDC) - mu * mu;
    float rstd = rsqrtf(var + 1e-6f);
    float* orow = g_xmod + (size_t)m * HIDC;
    #pragma unroll
    for (int i = 0; i < 12; i++) {
        int c = threadIdx.x + i * 256;
        float xn = (v[i] - mu) * rstd;
        orow[c] = xn * (1.f + g_mod[HIDC + c]) + g_mod[c];
    }
}

// ---------------- K3/K8: low-rank projector t = A @ ld^T  (block per row, warp per 4 ranks) ----------------
__global__ __launch_bounds__(256) void k_lowrank(const float* __restrict__ ld, int K, int sel) {
    const float* A = sel ? g_y : g_xmod;
    float* t = sel ? g_t2 : g_t1;
    int m = blockIdx.x;
    int w = threadIdx.x >> 5, lane = threadIdx.x & 31;
    const float* a = A + (size_t)m * K;
    const float* l0 = ld + (size_t)(w * 4 + 0) * K;
    const float* l1 = l0 + K;
    const float* l2 = l1 + K;
    const float* l3 = l2 + K;
    float a0 = 0.f, a1 = 0.f, a2 = 0.f, a3 = 0.f;
    for (int k = lane; k < K; k += 32) {
        float av = a[k];
        a0 += av * l0[k]; a1 += av * l1[k]; a2 += av * l2[k]; a3 += av * l3[k];
    }
    #pragma unroll
    for (int o = 16; o; o >>= 1) {
        a0 += __shfl_xor_sync(0xffffffffu, a0, o);
        a1 += __shfl_xor_sync(0xffffffffu, a1, o);
        a2 += __shfl_xor_sync(0xffffffffu, a2, o);
        a3 += __shfl_xor_sync(0xffffffffu, a3, o);
    }
    if (!lane) {
        float* tp = t + m * RK + w * 4;
        tp[0] = a0; tp[1] = a1; tp[2] = a2; tp[3] = a3;
    }
}

// ---------------- K4/K9: SGEMM 128x128x16, C = A@W^T + t@lu^T + bias (+residual/gate) ----------------
// EPI==1: A=g_xmod, C=g_qkv. EPI==2: A=g_y, C=out, out = x + gate*(..)
template <int EPI>
__global__ __launch_bounds__(256) void k_sgemm(const float* __restrict__ W,
                                               const float* __restrict__ bias,
                                               const float* __restrict__ lu,
                                               float* __restrict__ Cout,
                                               int K, int ldc,
                                               const float* __restrict__ xres) {
    __shared__ float As[16][132];
    __shared__ float Bs[16][132];
    const float* A  = (EPI == 1) ? g_xmod : g_y;
    const float* tl = (EPI == 1) ? g_t1 : g_t2;
    float* C        = (EPI == 1) ? g_qkv : Cout;

    int tid = threadIdx.x;
    int tx = tid & 15, ty = tid >> 4;
    int m0 = blockIdx.y << 7, n0 = blockIdx.x << 7;
    const float* Ab = A + (size_t)m0 * K;
    const float* Wb = W + (size_t)n0 * K;

    float acc[8][8];
    #pragma unroll
    for (int i = 0; i < 8; i++)
        #pragma unroll
        for (int j = 0; j < 8; j++) acc[i][j] = 0.f;

    for (int k0 = 0; k0 < K; k0 += 16) {
        #pragma unroll
        for (int l = 0; l < 2; l++) {
            int idx = tid + (l << 8);
            int r = idx >> 2, c4 = (idx & 3) << 2;
            float4 av = *(const float4*)(Ab + (size_t)r * K + k0 + c4);
            As[c4 + 0][r] = av.x; As[c4 + 1][r] = av.y; As[c4 + 2][r] = av.z; As[c4 + 3][r] = av.w;
            float4 wv = *(const float4*)(Wb + (size_t)r * K + k0 + c4);
            Bs[c4 + 0][r] = wv.x; Bs[c4 + 1][r] = wv.y; Bs[c4 + 2][r] = wv.z; Bs[c4 + 3][r] = wv.w;
        }
        __syncthreads();
        #pragma unroll
        for (int k = 0; k < 16; k++) {
            float4 a0 = *(const float4*)&As[k][ty * 8];
            float4 a1 = *(const float4*)&As[k][ty * 8 + 4];
            float4 b0 = *(const float4*)&Bs[k][tx * 8];
            float4 b1 = *(const float4*)&Bs[k][tx * 8 + 4];
            float ra[8] = {a0.x, a0.y, a0.z, a0.w, a1.x, a1.y, a1.z, a1.w};
            float rb[8] = {b0.x, b0.y, b0.z, b0.w, b1.x, b1.y, b1.z, b1.w};
            #pragma unroll
            for (int i = 0; i < 8; i++)
                #pragma unroll
                for (int j = 0; j < 8; j++) acc[i][j] += ra[i] * rb[j];
        }
        __syncthreads();
    }

    // low-rank epilogue: acc += t[m,:] * lu[n,:]^T (rank 32)
    #pragma unroll 4
    for (int r = 0; r < RK; r++) {
        float tv[8], lv[8];
        #pragma unroll
        for (int i = 0; i < 8; i++) tv[i] = tl[(size_t)(m0 + ty * 8 + i) * RK + r];
        #pragma unroll
        for (int j = 0; j < 8; j++) lv[j] = lu[(size_t)(n0 + tx * 8 + j) * RK + r];
        #pragma unroll
        for (int i = 0; i < 8; i++)
            #pragma unroll
            for (int j = 0; j < 8; j++) acc[i][j] += tv[i] * lv[j];
    }

    #pragma unroll
    for (int i = 0; i < 8; i++) {
        int m = m0 + ty * 8 + i;
        #pragma unroll
        for (int j = 0; j < 8; j++) {
            int n = n0 + tx * 8 + j;
            float v = acc[i][j] + bias[n];
            if (EPI == 2) v = xres[(size_t)m * ldc + n] + g_mod[2 * HIDC + n] * v;
            C[(size_t)m * ldc + n] = v;
        }
    }
}

// ---------------- K5: RMSNorm(q,k) + RoPE, in place in g_qkv ----------------
__global__ __launch_bounds__(128) void k_qknorm(const float* __restrict__ pe,
                                                const float* __restrict__ rqw,
                                                const float* __restrict__ rkw) {
    int l = blockIdx.x, h = blockIdx.y, d = threadIdx.x;
    size_t base = (size_t)l * NQKV + (size_t)h * HDC;
    float qv = g_qkv[base + d];
    float kv = g_qkv[base + HIDC + d];
    float q2 = qv * qv, k2 = kv * kv;
    #pragma unroll
    for (int o = 16; o; o >>= 1) {
        q2 += __shfl_xor_sync(0xffffffffu, q2, o);
        k2 += __shfl_xor_sync(0xffffffffu, k2, o);
    }
    __shared__ float sq[4], sk[4];
    int w = d >> 5, lane = d & 31;
    if (!lane) { sq[w] = q2; sk[w] = k2; }
    __syncthreads();
    float Q2 = sq[0] + sq[1] + sq[2] + sq[3];
    float K2 = sk[0] + sk[1] + sk[2] + sk[3];
    float qr = rsqrtf(Q2 * (1.f / HDC) + 1e-6f);
    float kr = rsqrtf(K2 * (1.f / HDC) + 1e-6f);
    float qn = qv * qr * rqw[d];
    float kn = kv * kr * rkw[d];
    int p = d >> 1, ii = d & 1;
    const float* rot = pe + (((size_t)l * 64 + p) * 2 + ii) * 2;
    float r0 = rot[0], r1 = rot[1];
    float qo = __shfl_xor_sync(0xffffffffu, qn, 1);
    float ko = __shfl_xor_sync(0xffffffffu, kn, 1);
    float qe = ii ? qo : qn, qod = ii ? qn : qo;
    float ke = ii ? ko : kn, kod = ii ? kn : ko;
    g_qkv[base + d] = r0 * qe + r1 * qod;
    g_qkv[base + HIDC + d] = r0 * ke + r1 * kod;
}

// ---------------- K6: flash attention (64q x 64k tiles, fp32, online softmax) ----------------
// smem: Qs[64][128] Ks[64][129] Vs[64][128] S[64][65] rm/rl/rc[64]
constexpr int ATT_SMEM = (64 * 128 + 64 * 129 + 64 * 128 + 64 * 65 + 192) * 4;  // 115968 B

__global__ __launch_bounds__(256) void k_attn() {
    extern __shared__ float sm[];
    float* Qs = sm;                  // stride 128
    float* Ks = Qs + 64 * 128;       // stride 129 (padded)
    float* Vs = Ks + 64 * 129;       // stride 128
    float* S  = Vs + 64 * 128;       // stride 65
    float* rm = S + 64 * 65;
    float* rl = rm + 64;
    float* rc = rl + 64;

    int tid = threadIdx.x;
    int q0 = blockIdx.x * 64;
    int h = blockIdx.y;
    const size_t hq = (size_t)h * HDC;  // wait: head offset is h*HDC? no -> h*HD
    const size_t ho = (size_t)h * HDC / NHC * NHC;  // (unused, see below)
    (void)hq; (void)ho;
    const size_t hoff = (size_t)h * HDC;  // placeholder
    (void)hoff;
    const size_t hbase = (size_t)h * 128;  // h * HD

    // load Q tile
    for (int i = tid; i < 64 * 32; i += 256) {
        int r = i >> 5, d4 = (i & 31) << 2;
        float4 v = *(const float4*)(g_qkv + (size_t)(q0 + r) * NQKV + hbase + d4);
        *(float4*)(Qs + r * 128 + d4) = v;
    }
    if (tid < 64) { rm[tid] = -1e30f; rl[tid] = 0.f; }
    float acc[32];
    #pragma unroll
    for (int d = 0; d < 32; d++) acc[d] = 0.f;
    int qi = tid & 63, dg = tid >> 6;

    for (int kb = 0; kb < LL / 64; kb++) {
        __syncthreads();
        int k0 = kb * 64;
        for (int i = tid; i < 64 * 32; i += 256) {
            int r = i >> 5, d4 = (i & 31) << 2;
            const float* kp = g_qkv + (size_t)(k0 + r) * NQKV + HIDC + hbase + d4;
            float4 kv = *(const float4*)kp;
            Ks[r * 129 + d4 + 0] = kv.x; Ks[r * 129 + d4 + 1] = kv.y;
            Ks[r * 129 + d4 + 2] = kv.z; Ks[r * 129 + d4 + 3] = kv.w;
            float4 vv = *(const float4*)(kp + HIDC);
            *(float4*)(Vs + r * 128 + d4) = vv;
        }
        __syncthreads();
        // S = scale * Q @ K^T  (thread: 4 q-rows x 4 k-cols)
        {
            int qr = (tid >> 4) << 2;   // 2 distinct per warp -> near-broadcast on Qs
            int kc = (tid & 15) << 2;   // 16 distinct, Ks padded to 129
            float s[4][4];
            #pragma unroll
            for (int i = 0; i < 4; i++)
                #pragma unroll
                for (int j = 0; j < 4; j++) s[i][j] = 0.f;
            for (int d = 0; d < 128; d++) {
                float qv0 = Qs[(qr + 0) * 128 + d], qv1 = Qs[(qr + 1) * 128 + d];
                float qv2 = Qs[(qr + 2) * 128 + d], qv3 = Qs[(qr + 3) * 128 + d];
                float kv0 = Ks[(kc + 0) * 129 + d], kv1 = Ks[(kc + 1) * 129 + d];
                float kv2 = Ks[(kc + 2) * 129 + d], kv3 = Ks[(kc + 3) * 129 + d];
                s[0][0] += qv0 * kv0; s[0][1] += qv0 * kv1; s[0][2] += qv0 * kv2; s[0][3] += qv0 * kv3;
                s[1][0] += qv1 * kv0; s[1][1] += qv1 * kv1; s[1][2] += qv1 * kv2; s[1][3] += qv1 * kv3;
                s[2][0] += qv2 * kv0; s[2][1] += qv2 * kv1; s[2][2] += qv2 * kv2; s[2][3] += qv2 * kv3;
                s[3][0] += qv3 * kv0; s[3][1] += qv3 * kv1; s[3][2] += qv3 * kv2; s[3][3] += qv3 * kv3;
            }
            const float scale = 0.08838834764831845f;  // 1/sqrt(128)
            #pragma unroll
            for (int i = 0; i < 4; i++)
                #pragma unroll
                for (int j = 0; j < 4; j++)
                    S[(qr + i) * 65 + kc + j] = s[i][j] * scale;
        }
        __syncthreads();
        // online softmax row update (threads 0..63, one row each)
        if (tid < 64) {
            float mo = rm[tid];
            float mx = mo;
            float* srow = S + tid * 65;
            #pragma unroll 8
            for (int j = 0; j < 64; j++) mx = fmaxf(mx, srow[j]);
            float corr = expf(mo - mx);
            float sum = 0.f;
            #pragma unroll 8
            for (int j = 0; j < 64; j++) {
                float pv = expf(srow[j] - mx);
                srow[j] = pv;
                sum += pv;
            }
            rl[tid] = rl[tid] * corr + sum;
            rm[tid] = mx;
            rc[tid] = corr;
        }
        __syncthreads();
        // O update (thread: row qi, dims [dg*32, dg*32+32))
        {
            float c = rc[qi];
            #pragma unroll
            for (int d = 0; d < 32; d++) acc[d] *= c;
            const float* srow = S + qi * 65;
            for (int j = 0; j < 64; j++) {
                float pv = srow[j];
                const float* vrow = Vs + j * 128 + dg * 32;
                #pragma unroll
                for (int d = 0; d < 32; d++) acc[d] += pv * vrow[d];
            }
        }
    }
    float inv = 1.f / rl[qi];
    float* orow = g_y + (size_t)(q0 + qi) * NCAT + hbase + dg * 32;
    #pragma unroll
    for (int d = 0; d < 32; d++) orow[d] = acc[d] * inv;
}

// ---------------- K7: gelu(tanh) on mlp_h -> g_y[:, 3072:] ----------------
__global__ __launch_bounds__(256) void k_gelu() {
    int m = blockIdx.y;
    int j = blockIdx.x * 256 + threadIdx.x;
    float v = g_qkv[(size_t)m * NQKV + D3H + j];
    float t = tanhf(0.7978845608028654f * (v + 0.044715f * v * v * v));
    g_y[(size_t)m * NCAT + HIDC + j] = 0.5f * v * (1.f + t);
}

// ---------------- launch ----------------
extern "C" void kernel_launch(void* const* d_in, const int* in_sizes, int n_in,
                              void* d_out, int out_size) {
    const float* x     = (const float*)d_in[0];
    const float* vec   = (const float*)d_in[1];
    const float* pe    = (const float*)d_in[2];
    const float* mod_w = (const float*)d_in[3];
    const float* mod_b = (const float*)d_in[4];
    const float* w1    = (const float*)d_in[5];
    const float* b1    = (const float*)d_in[6];
    const float* ld1   = (const float*)d_in[7];
    const float* lu1   = (const float*)d_in[8];
    const float* w2    = (const float*)d_in[9];
    const float* b2    = (const float*)d_in[10];
    const float* ld2   = (const float*)d_in[11];
    const float* lu2   = (const float*)d_in[12];
    const float* rqw   = (const float*)d_in[13];
    const float* rkw   = (const float*)d_in[14];
    float* out = (float*)d_out;

    cudaFuncSetAttribute(k_attn, cudaFuncAttributeMaxDynamicSharedMemorySize, ATT_SMEM);

    k_mod<<<D3H / 8, 256>>>(vec, mod_w, mod_b);
    k_ln<<<LL, 256>>>(x);
    k_lowrank<<<LL, 256>>>(ld1, HIDC, 0);
    {
        dim3 g(NQKV / 128, LL / 128);
        k_sgemm<1><<<g, 256>>>(w1, b1, lu1, nullptr, HIDC, NQKV, nullptr);
    }
    {
        dim3 g(LL, NHC);
        k_qknorm<<<g, 128>>>(pe, rqw, rkw);
    }
    {
        dim3 g(LL / 64, NHC);
        k_attn<<<g, 256, ATT_SMEM>>>();
    }
    {
        dim3 g(MLPC / 256, LL);
        k_gelu<<<g, 256>>>();
    }
    k_lowrank<<<LL, 256>>>(ld2, NCAT, 1);
    {
        dim3 g(HIDC / 128, LL / 128);
        k_sgemm<2><<<g, 256>>>(w2, b2, lu2, out, NCAT, HIDC, x);
    }
}

// round 2
// speedup vs baseline: 1.8130x; 1.8130x over previous
#include <cuda_runtime.h>
#include <math.h>

// ---------------- problem constants ----------------
constexpr int LL   = 4608;
constexpr int HIDC = 3072;
constexpr int NHC  = 24;
constexpr int HDC  = 128;
constexpr int MLPC = 12288;
constexpr int RK   = 32;
constexpr int D3H  = 3 * HIDC;          // 9216
constexpr int NQKV = 3 * HIDC + MLPC;   // 21504
constexpr int NCAT = HIDC + MLPC;       // 15360

// ---------------- scratch (device globals; no allocation allowed) ----------------
__device__ float g_mod[D3H];                       // shift|scale|gate
__device__ float g_xmod[(size_t)LL * HIDC];
__device__ float g_qkv[(size_t)LL * NQKV];
__device__ float g_y[(size_t)LL * NCAT];           // attn | gelu(mlp)
__device__ float g_t1[LL * RK];
__device__ float g_t2[LL * RK];

// ---------------- K1: mod = silu(vec) @ mod_w^T + mod_b ----------------
__global__ __launch_bounds__(256) void k_mod(const float* __restrict__ vec,
                                             const float* __restrict__ mod_w,
                                             const float* __restrict__ mod_b) {
    int j = blockIdx.x * 8 + (threadIdx.x >> 5);
    int lane = threadIdx.x & 31;
    if (j >= D3H) return;
    const float* wr = mod_w + (size_t)j * HIDC;
    float acc = 0.f;
    for (int k = lane; k < HIDC; k += 32) {
        float s = vec[k];
        float si = s / (1.f + expf(-s));
        acc += si * wr[k];
    }
    #pragma unroll
    for (int o = 16; o; o >>= 1) acc += __shfl_xor_sync(0xffffffffu, acc, o);
    if (lane == 0) g_mod[j] = acc + mod_b[j];
}

// ---------------- K2: LayerNorm + modulation -> g_xmod ----------------
__global__ __launch_bounds__(256) void k_ln(const float* __restrict__ x) {
    __shared__ float rs[8], rs2[8];
    int m = blockIdx.x;
    const float* row = x + (size_t)m * HIDC;
    float v[12];
    float s = 0.f, s2 = 0.f;
    #pragma unroll
    for (int i = 0; i < 12; i++) {
        v[i] = row[threadIdx.x + i * 256];
        s += v[i]; s2 += v[i] * v[i];
    }
    int lane = threadIdx.x & 31, w = threadIdx.x >> 5;
    #pragma unroll
    for (int o = 16; o; o >>= 1) {
        s  += __shfl_xor_sync(0xffffffffu, s, o);
        s2 += __shfl_xor_sync(0xffffffffu, s2, o);
    }
    if (!lane) { rs[w] = s; rs2[w] = s2; }
    __syncthreads();
    float S = 0.f, S2 = 0.f;
    #pragma unroll
    for (int i = 0; i < 8; i++) { S += rs[i]; S2 += rs2[i]; }
    float mu = S * (1.f / HIDC);
    float var = S2 * (1.f / HIDC) - mu * mu;
    float rstd = rsqrtf(var + 1e-6f);
    float* orow = g_xmod + (size_t)m * HIDC;
    #pragma unroll
    for (int i = 0; i < 12; i++) {
        int c = threadIdx.x + i * 256;
        float xn = (v[i] - mu) * rstd;
        orow[c] = xn * (1.f + g_mod[HIDC + c]) + g_mod[c];
    }
}

// ---------------- K3/K8: low-rank projector t = A @ ld^T ----------------
__global__ __launch_bounds__(256) void k_lowrank(const float* __restrict__ ld, int K, int sel) {
    const float* A = sel ? g_y : g_xmod;
    float* t = sel ? g_t2 : g_t1;
    int m = blockIdx.x;
    int w = threadIdx.x >> 5, lane = threadIdx.x & 31;
    const float* a = A + (size_t)m * K;
    const float* l0 = ld + (size_t)(w * 4 + 0) * K;
    const float* l1 = l0 + K;
    const float* l2 = l1 + K;
    const float* l3 = l2 + K;
    float a0 = 0.f, a1 = 0.f, a2 = 0.f, a3 = 0.f;
    for (int k = lane; k < K; k += 32) {
        float av = a[k];
        a0 += av * l0[k]; a1 += av * l1[k]; a2 += av * l2[k]; a3 += av * l3[k];
    }
    #pragma unroll
    for (int o = 16; o; o >>= 1) {
        a0 += __shfl_xor_sync(0xffffffffu, a0, o);
        a1 += __shfl_xor_sync(0xffffffffu, a1, o);
        a2 += __shfl_xor_sync(0xffffffffu, a2, o);
        a3 += __shfl_xor_sync(0xffffffffu, a3, o);
    }
    if (!lane) {
        float* tp = t + m * RK + w * 4;
        tp[0] = a0; tp[1] = a1; tp[2] = a2; tp[3] = a3;
    }
}

// ---------------- tf32 tensor-core GEMM ----------------
// C[M,N] = [A | t] @ [W | lu]^T + bias (+residual/gate for EPI==2)
// block tile 128x128, 512 threads (4x4 warps, warp tile 32x32), k-tile 32.
__device__ __forceinline__ unsigned f2tf(float f) {
    unsigned u;
    asm("cvt.rna.tf32.f32 %0, %1;" : "=r"(u) : "f"(f));
    return u;
}
__device__ __forceinline__ void mma8(float* c, const unsigned* a, const unsigned* b) {
    asm volatile(
        "mma.sync.aligned.m16n8k8.row.col.f32.tf32.tf32.f32 "
        "{%0,%1,%2,%3}, {%4,%5,%6,%7}, {%8,%9}, {%0,%1,%2,%3};"
        : "+f"(c[0]), "+f"(c[1]), "+f"(c[2]), "+f"(c[3])
        : "r"(a[0]), "r"(a[1]), "r"(a[2]), "r"(a[3]), "r"(b[0]), "r"(b[1]));
}

constexpr int SROW = 36;                    // smem row stride (words): conflict-free frags
constexpr int MAT_WORDS = 128 * SROW;       // 4608 words per matrix tile
constexpr int STAGE_WORDS = 2 * MAT_WORDS;  // A + B
constexpr int GEMM_SMEM = 2 * STAGE_WORDS * 4;  // 73728 B

template <int EPI, int GRP>
__global__ __launch_bounds__(512) void k_gemm(const float* __restrict__ W,
                                              const float* __restrict__ bias,
                                              const float* __restrict__ lu,
                                              float* __restrict__ Cout,
                                              int K, int N, int ldc,
                                              const float* __restrict__ xres) {
    extern __shared__ unsigned smem_u[];
    const float* A  = (EPI == 1) ? g_xmod : g_y;
    const float* TL = (EPI == 1) ? g_t1 : g_t2;
    float* C        = (EPI == 1) ? g_qkv : Cout;

    const int NMB = LL / 128;   // 36
    const int NNB = N / 128;

    // swizzled block mapping: groups of GRP m-blocks, m fastest inside group
    int bid = blockIdx.x;
    int group = bid / (GRP * NNB);
    int within = bid - group * (GRP * NNB);
    int mb = group * GRP + (within % GRP);
    int nb = within / GRP;
    (void)NMB;
    int m0 = mb << 7, n0 = nb << 7;

    int tid = threadIdx.x;
    int lane = tid & 31;
    int wid = tid >> 5;
    int wm = wid >> 2, wn = wid & 3;        // 4x4 warp grid
    int g = lane >> 2, tg = lane & 3;

    const int KTm = K / 32;                 // main k-tiles
    const int KTt = KTm + 1;                // + low-rank tile

    float acc[2][4][4];
    #pragma unroll
    for (int i = 0; i < 2; i++)
        #pragma unroll
        for (int j = 0; j < 4; j++)
            #pragma unroll
            for (int q = 0; q < 4; q++) acc[i][j][q] = 0.f;

    // loader chunk indices: 1024 float4 chunks per matrix, 2 per thread
    int c0 = tid, c1 = tid + 512;
    int ar0 = c0 >> 3, ak0 = (c0 & 7) << 2;
    int ar1 = c1 >> 3, ak1 = (c1 & 7) << 2;

    auto ldA = [&](int kt, int row, int k4) -> float4 {
        if (kt < KTm)
            return *(const float4*)(A + (size_t)(m0 + row) * K + kt * 32 + k4);
        return *(const float4*)(TL + (size_t)(m0 + row) * RK + k4);
    };
    auto ldB = [&](int kt, int row, int k4) -> float4 {
        if (kt < KTm)
            return *(const float4*)(W + (size_t)(n0 + row) * K + kt * 32 + k4);
        return *(const float4*)(lu + (size_t)(n0 + row) * RK + k4);
    };
    auto stTile = [&](int s, float4 a0v, float4 a1v, float4 b0v, float4 b1v) {
        unsigned* sA = smem_u + s * STAGE_WORDS;
        unsigned* sB = sA + MAT_WORDS;
        uint4 u;
        u.x = f2tf(a0v.x); u.y = f2tf(a0v.y); u.z = f2tf(a0v.z); u.w = f2tf(a0v.w);
        *(uint4*)(sA + ar0 * SROW + ak0) = u;
        u.x = f2tf(a1v.x); u.y = f2tf(a1v.y); u.z = f2tf(a1v.z); u.w = f2tf(a1v.w);
        *(uint4*)(sA + ar1 * SROW + ak1) = u;
        u.x = f2tf(b0v.x); u.y = f2tf(b0v.y); u.z = f2tf(b0v.z); u.w = f2tf(b0v.w);
        *(uint4*)(sB + ar0 * SROW + ak0) = u;
        u.x = f2tf(b1v.x); u.y = f2tf(b1v.y); u.z = f2tf(b1v.z); u.w = f2tf(b1v.w);
        *(uint4*)(sB + ar1 * SROW + ak1) = u;
    };

    // prologue: tile 0 -> stage 0
    {
        float4 a0v = ldA(0, ar0, ak0), a1v = ldA(0, ar1, ak1);
        float4 b0v = ldB(0, ar0, ak0), b1v = ldB(0, ar1, ak1);
        stTile(0, a0v, a1v, b0v, b1v);
    }
    __syncthreads();

    for (int kt = 0; kt < KTt; kt++) {
        int cur = kt & 1;
        float4 a0v, a1v, b0v, b1v;
        bool more = (kt + 1 < KTt);
        if (more) {
            a0v = ldA(kt + 1, ar0, ak0); a1v = ldA(kt + 1, ar1, ak1);
            b0v = ldB(kt + 1, ar0, ak0); b1v = ldB(kt + 1, ar1, ak1);
        }
        const unsigned* sA = smem_u + cur * STAGE_WORDS;
        const unsigned* sB = sA + MAT_WORDS;
        #pragma unroll
        for (int ks = 0; ks < 4; ks++) {
            unsigned af[2][4], bf[4][2];
            #pragma unroll
            for (int fm = 0; fm < 2; fm++) {
                int row = wm * 32 + fm * 16 + g;
                int col = ks * 8 + tg;
                af[fm][0] = sA[row * SROW + col];
                af[fm][1] = sA[(row + 8) * SROW + col];
                af[fm][2] = sA[row * SROW + col + 4];
                af[fm][3] = sA[(row + 8) * SROW + col + 4];
            }
            #pragma unroll
            for (int fn = 0; fn < 4; fn++) {
                int n = wn * 32 + fn * 8 + g;
                bf[fn][0] = sB[n * SROW + ks * 8 + tg];
                bf[fn][1] = sB[n * SROW + ks * 8 + tg + 4];
            }
            #pragma unroll
            for (int fm = 0; fm < 2; fm++)
                #pragma unroll
                for (int fn = 0; fn < 4; fn++)
                    mma8(acc[fm][fn], af[fm], bf[fn]);
        }
        if (more) stTile(1 - cur, a0v, a1v, b0v, b1v);
        __syncthreads();
    }

    // epilogue: bias (+ residual & gate for EPI==2), float2 stores
    #pragma unroll
    for (int fm = 0; fm < 2; fm++) {
        int r0 = m0 + wm * 32 + fm * 16 + g;
        int r1 = r0 + 8;
        #pragma unroll
        for (int fn = 0; fn < 4; fn++) {
            int cc = n0 + wn * 32 + fn * 8 + 2 * tg;
            float v0 = acc[fm][fn][0] + bias[cc];
            float v1 = acc[fm][fn][1] + bias[cc + 1];
            float v2 = acc[fm][fn][2] + bias[cc];
            float v3 = acc[fm][fn][3] + bias[cc + 1];
            if (EPI == 2) {
                float gt0 = g_mod[2 * HIDC + cc], gt1 = g_mod[2 * HIDC + cc + 1];
                v0 = xres[(size_t)r0 * ldc + cc]     + gt0 * v0;
                v1 = xres[(size_t)r0 * ldc + cc + 1] + gt1 * v1;
                v2 = xres[(size_t)r1 * ldc + cc]     + gt0 * v2;
                v3 = xres[(size_t)r1 * ldc + cc + 1] + gt1 * v3;
            }
            float2 p0 = make_float2(v0, v1);
            float2 p1 = make_float2(v2, v3);
            *(float2*)(C + (size_t)r0 * ldc + cc) = p0;
            *(float2*)(C + (size_t)r1 * ldc + cc) = p1;
        }
    }
}

// ---------------- K5: RMSNorm(q,k) + RoPE, in place in g_qkv ----------------
__global__ __launch_bounds__(128) void k_qknorm(const float* __restrict__ pe,
                                                const float* __restrict__ rqw,
                                                const float* __restrict__ rkw) {
    int l = blockIdx.x, h = blockIdx.y, d = threadIdx.x;
    size_t base = (size_t)l * NQKV + (size_t)h * 128;
    float qv = g_qkv[base + d];
    float kv = g_qkv[base + HIDC + d];
    float q2 = qv * qv, k2 = kv * kv;
    #pragma unroll
    for (int o = 16; o; o >>= 1) {
        q2 += __shfl_xor_sync(0xffffffffu, q2, o);
        k2 += __shfl_xor_sync(0xffffffffu, k2, o);
    }
    __shared__ float sq[4], sk[4];
    int w = d >> 5, lane = d & 31;
    if (!lane) { sq[w] = q2; sk[w] = k2; }
    __syncthreads();
    float Q2 = sq[0] + sq[1] + sq[2] + sq[3];
    float K2 = sk[0] + sk[1] + sk[2] + sk[3];
    float qr = rsqrtf(Q2 * (1.f / HDC) + 1e-6f);
    float kr = rsqrtf(K2 * (1.f / HDC) + 1e-6f);
    float qn = qv * qr * rqw[d];
    float kn = kv * kr * rkw[d];
    int p = d >> 1, ii = d & 1;
    const float* rot = pe + (((size_t)l * 64 + p) * 2 + ii) * 2;
    float r0 = rot[0], r1 = rot[1];
    float qo = __shfl_xor_sync(0xffffffffu, qn, 1);
    float ko = __shfl_xor_sync(0xffffffffu, kn, 1);
    float qe = ii ? qo : qn, qod = ii ? qn : qo;
    float ke = ii ? ko : kn, kod = ii ? kn : ko;
    g_qkv[base + d] = r0 * qe + r1 * qod;
    g_qkv[base + HIDC + d] = r0 * ke + r1 * kod;
}

// ---------------- K6: flash attention (64q x 64k tiles, fp32) ----------------
constexpr int ATT_SMEM = (64 * 128 + 64 * 129 + 64 * 128 + 64 * 65 + 192) * 4;

__global__ __launch_bounds__(256) void k_attn() {
    extern __shared__ float sm[];
    float* Qs = sm;
    float* Ks = Qs + 64 * 128;
    float* Vs = Ks + 64 * 129;
    float* S  = Vs + 64 * 128;
    float* rm = S + 64 * 65;
    float* rl = rm + 64;
    float* rc = rl + 64;

    int tid = threadIdx.x;
    int q0 = blockIdx.x * 64;
    int h = blockIdx.y;
    const size_t hbase = (size_t)h * 128;

    for (int i = tid; i < 64 * 32; i += 256) {
        int r = i >> 5, d4 = (i & 31) << 2;
        float4 v = *(const float4*)(g_qkv + (size_t)(q0 + r) * NQKV + hbase + d4);
        *(float4*)(Qs + r * 128 + d4) = v;
    }
    if (tid < 64) { rm[tid] = -1e30f; rl[tid] = 0.f; }
    float acc[32];
    #pragma unroll
    for (int d = 0; d < 32; d++) acc[d] = 0.f;
    int qi = tid & 63, dg = tid >> 6;

    for (int kb = 0; kb < LL / 64; kb++) {
        __syncthreads();
        int k0 = kb * 64;
        for (int i = tid; i < 64 * 32; i += 256) {
            int r = i >> 5, d4 = (i & 31) << 2;
            const float* kp = g_qkv + (size_t)(k0 + r) * NQKV + HIDC + hbase + d4;
            float4 kv = *(const float4*)kp;
            Ks[r * 129 + d4 + 0] = kv.x; Ks[r * 129 + d4 + 1] = kv.y;
            Ks[r * 129 + d4 + 2] = kv.z; Ks[r * 129 + d4 + 3] = kv.w;
            float4 vv = *(const float4*)(kp + HIDC);
            *(float4*)(Vs + r * 128 + d4) = vv;
        }
        __syncthreads();
        {
            int qr = (tid >> 4) << 2;
            int kc = (tid & 15) << 2;
            float s[4][4];
            #pragma unroll
            for (int i = 0; i < 4; i++)
                #pragma unroll
                for (int j = 0; j < 4; j++) s[i][j] = 0.f;
            for (int d = 0; d < 128; d++) {
                float qv0 = Qs[(qr + 0) * 128 + d], qv1 = Qs[(qr + 1) * 128 + d];
                float qv2 = Qs[(qr + 2) * 128 + d], qv3 = Qs[(qr + 3) * 128 + d];
                float kv0 = Ks[(kc + 0) * 129 + d], kv1 = Ks[(kc + 1) * 129 + d];
                float kv2 = Ks[(kc + 2) * 129 + d], kv3 = Ks[(kc + 3) * 129 + d];
                s[0][0] += qv0 * kv0; s[0][1] += qv0 * kv1; s[0][2] += qv0 * kv2; s[0][3] += qv0 * kv3;
                s[1][0] += qv1 * kv0; s[1][1] += qv1 * kv1; s[1][2] += qv1 * kv2; s[1][3] += qv1 * kv3;
                s[2][0] += qv2 * kv0; s[2][1] += qv2 * kv1; s[2][2] += qv2 * kv2; s[2][3] += qv2 * kv3;
                s[3][0] += qv3 * kv0; s[3][1] += qv3 * kv1; s[3][2] += qv3 * kv2; s[3][3] += qv3 * kv3;
            }
            const float scale = 0.08838834764831845f;
            #pragma unroll
            for (int i = 0; i < 4; i++)
                #pragma unroll
                for (int j = 0; j < 4; j++)
                    S[(qr + i) * 65 + kc + j] = s[i][j] * scale;
        }
        __syncthreads();
        if (tid < 64) {
            float mo = rm[tid];
            float mx = mo;
            float* srow = S + tid * 65;
            #pragma unroll 8
            for (int j = 0; j < 64; j++) mx = fmaxf(mx, srow[j]);
            float corr = expf(mo - mx);
            float sum = 0.f;
            #pragma unroll 8
            for (int j = 0; j < 64; j++) {
                float pv = expf(srow[j] - mx);
                srow[j] = pv;
                sum += pv;
            }
            rl[tid] = rl[tid] * corr + sum;
            rm[tid] = mx;
            rc[tid] = corr;
        }
        __syncthreads();
        {
            float c = rc[qi];
            #pragma unroll
            for (int d = 0; d < 32; d++) acc[d] *= c;
            const float* srow = S + qi * 65;
            for (int j = 0; j < 64; j++) {
                float pv = srow[j];
                const float* vrow = Vs + j * 128 + dg * 32;
                #pragma unroll
                for (int d = 0; d < 32; d++) acc[d] += pv * vrow[d];
            }
        }
    }
    float inv = 1.f / rl[qi];
    float* orow = g_y + (size_t)(q0 + qi) * NCAT + hbase + dg * 32;
    #pragma unroll
    for (int d = 0; d < 32; d++) orow[d] = acc[d] * inv;
}

// ---------------- K7: gelu(tanh) on mlp_h -> g_y[:, 3072:] ----------------
__global__ __launch_bounds__(256) void k_gelu() {
    int m = blockIdx.y;
    int j = blockIdx.x * 256 + threadIdx.x;
    float v = g_qkv[(size_t)m * NQKV + D3H + j];
    float t = tanhf(0.7978845608028654f * (v + 0.044715f * v * v * v));
    g_y[(size_t)m * NCAT + HIDC + j] = 0.5f * v * (1.f + t);
}

// ---------------- launch ----------------
extern "C" void kernel_launch(void* const* d_in, const int* in_sizes, int n_in,
                              void* d_out, int out_size) {
    const float* x     = (const float*)d_in[0];
    const float* vec   = (const float*)d_in[1];
    const float* pe    = (const float*)d_in[2];
    const float* mod_w = (const float*)d_in[3];
    const float* mod_b = (const float*)d_in[4];
    const float* w1    = (const float*)d_in[5];
    const float* b1    = (const float*)d_in[6];
    const float* ld1   = (const float*)d_in[7];
    const float* lu1   = (const float*)d_in[8];
    const float* w2    = (const float*)d_in[9];
    const float* b2    = (const float*)d_in[10];
    const float* ld2   = (const float*)d_in[11];
    const float* lu2   = (const float*)d_in[12];
    const float* rqw   = (const float*)d_in[13];
    const float* rkw   = (const float*)d_in[14];
    float* out = (float*)d_out;

    cudaFuncSetAttribute(k_attn, cudaFuncAttributeMaxDynamicSharedMemorySize, ATT_SMEM);
    cudaFuncSetAttribute((const void*)k_gemm<1, 12>, cudaFuncAttributeMaxDynamicSharedMemorySize, GEMM_SMEM);
    cudaFuncSetAttribute((const void*)k_gemm<2, 6>,  cudaFuncAttributeMaxDynamicSharedMemorySize, GEMM_SMEM);

    k_mod<<<D3H / 8, 256>>>(vec, mod_w, mod_b);
    k_ln<<<LL, 256>>>(x);
    k_lowrank<<<LL, 256>>>(ld1, HIDC, 0);
    {
        int nblocks = (LL / 128) * (NQKV / 128);   // 36 * 168
        k_gemm<1, 12><<<nblocks, 512, GEMM_SMEM>>>(w1, b1, lu1, nullptr, HIDC, NQKV, NQKV, nullptr);
    }
    {
        dim3 g(LL, NHC);
        k_qknorm<<<g, 128>>>(pe, rqw, rkw);
    }
    {
        dim3 g(LL / 64, NHC);
        k_attn<<<g, 256, ATT_SMEM>>>();
    }
    {
        dim3 g(MLPC / 256, LL);
        k_gelu<<<g, 256>>>();
    }
    k_lowrank<<<LL, 256>>>(ld2, NCAT, 1);
    {
        int nblocks = (LL / 128) * (HIDC / 128);   // 36 * 24
        k_gemm<2, 6><<<nblocks, 512, GEMM_SMEM>>>(w2, b2, lu2, out, NCAT, HIDC, HIDC, x);
    }
}

// round 3
// speedup vs baseline: 3.3769x; 1.8626x over previous
#include <cuda_runtime.h>
#include <math.h>

// ---------------- problem constants ----------------
constexpr int LL   = 4608;
constexpr int HIDC = 3072;
constexpr int NHC  = 24;
constexpr int HDC  = 128;
constexpr int MLPC = 12288;
constexpr int RK   = 32;
constexpr int D3H  = 3 * HIDC;          // 9216
constexpr int NQKV = 3 * HIDC + MLPC;   // 21504
constexpr int NCAT = HIDC + MLPC;       // 15360

// ---------------- scratch (device globals) ----------------
__device__ float g_mod[D3H];
__device__ float g_xmod[(size_t)LL * HIDC];
__device__ float g_qkv[(size_t)LL * NQKV];
__device__ float g_y[(size_t)LL * NCAT];
__device__ float g_t1[LL * RK];
__device__ float g_t2[LL * RK];
// pre-rounded (tf32) weights
__device__ float g_w1r[(size_t)NQKV * HIDC];
__device__ float g_w2r[(size_t)HIDC * NCAT];
__device__ float g_lu1r[NQKV * RK];
__device__ float g_lu2r[HIDC * RK];

// ---------------- helpers ----------------
__device__ __forceinline__ unsigned f2tf(float f) {
    unsigned u;
    asm("cvt.rna.tf32.f32 %0, %1;" : "=r"(u) : "f"(f));
    return u;
}
__device__ __forceinline__ float f2tff(float f) { return __uint_as_float(f2tf(f)); }

__device__ __forceinline__ void mma8(float* c, const unsigned* a, const unsigned* b) {
    asm volatile(
        "mma.sync.aligned.m16n8k8.row.col.f32.tf32.tf32.f32 "
        "{%0,%1,%2,%3}, {%4,%5,%6,%7}, {%8,%9}, {%0,%1,%2,%3};"
        : "+f"(c[0]), "+f"(c[1]), "+f"(c[2]), "+f"(c[3])
        : "r"(a[0]), "r"(a[1]), "r"(a[2]), "r"(a[3]), "r"(b[0]), "r"(b[1]));
}
__device__ __forceinline__ void cp16(void* s, const void* g) {
    unsigned sa = (unsigned)__cvta_generic_to_shared(s);
    asm volatile("cp.async.cg.shared.global [%0], [%1], 16;" :: "r"(sa), "l"(g));
}
#define CP_COMMIT() asm volatile("cp.async.commit_group;")
#define CP_WAIT(N)  asm volatile("cp.async.wait_group %0;" :: "n"(N))

// ---------------- K0: round weights to tf32 ----------------
__global__ __launch_bounds__(256) void k_round(const float* __restrict__ src, int which) {
    float* dst = which == 0 ? g_w1r : which == 1 ? g_w2r : which == 2 ? g_lu1r : g_lu2r;
    size_t i = ((size_t)blockIdx.x * 256 + threadIdx.x) * 4;
    float4 v = *(const float4*)(src + i);
    v.x = f2tff(v.x); v.y = f2tff(v.y); v.z = f2tff(v.z); v.w = f2tff(v.w);
    *(float4*)(dst + i) = v;
}

// ---------------- K1: mod = silu(vec) @ mod_w^T + mod_b ----------------
__global__ __launch_bounds__(256) void k_mod(const float* __restrict__ vec,
                                             const float* __restrict__ mod_w,
                                             const float* __restrict__ mod_b) {
    int j = blockIdx.x * 8 + (threadIdx.x >> 5);
    int lane = threadIdx.x & 31;
    if (j >= D3H) return;
    const float* wr = mod_w + (size_t)j * HIDC;
    float acc = 0.f;
    for (int k = lane; k < HIDC; k += 32) {
        float s = vec[k];
        acc += (s / (1.f + expf(-s))) * wr[k];
    }
    #pragma unroll
    for (int o = 16; o; o >>= 1) acc += __shfl_xor_sync(0xffffffffu, acc, o);
    if (lane == 0) g_mod[j] = acc + mod_b[j];
}

// ---------------- K2: LayerNorm + modulation -> g_xmod (tf32-rounded) ----------------
__global__ __launch_bounds__(256) void k_ln(const float* __restrict__ x) {
    __shared__ float rs[8], rs2[8];
    int m = blockIdx.x;
    const float* row = x + (size_t)m * HIDC;
    float v[12];
    float s = 0.f, s2 = 0.f;
    #pragma unroll
    for (int i = 0; i < 12; i++) {
        v[i] = row[threadIdx.x + i * 256];
        s += v[i]; s2 += v[i] * v[i];
    }
    int lane = threadIdx.x & 31, w = threadIdx.x >> 5;
    #pragma unroll
    for (int o = 16; o; o >>= 1) {
        s  += __shfl_xor_sync(0xffffffffu, s, o);
        s2 += __shfl_xor_sync(0xffffffffu, s2, o);
    }
    if (!lane) { rs[w] = s; rs2[w] = s2; }
    __syncthreads();
    float S = 0.f, S2 = 0.f;
    #pragma unroll
    for (int i = 0; i < 8; i++) { S += rs[i]; S2 += rs2[i]; }
    float mu = S * (1.f / HIDC);
    float var = S2 * (1.f / HIDC) - mu * mu;
    float rstd = rsqrtf(var + 1e-6f);
    float* orow = g_xmod + (size_t)m * HIDC;
    #pragma unroll
    for (int i = 0; i < 12; i++) {
        int c = threadIdx.x + i * 256;
        float xn = (v[i] - mu) * rstd;
        orow[c] = f2tff(xn * (1.f + g_mod[HIDC + c]) + g_mod[c]);
    }
}

// ---------------- K3/K8: low-rank projector t = A @ ld^T (tf32-rounded out) ----------------
__global__ __launch_bounds__(256) void k_lowrank(const float* __restrict__ ld, int K, int sel) {
    const float* A = sel ? g_y : g_xmod;
    float* t = sel ? g_t2 : g_t1;
    int m = blockIdx.x;
    int w = threadIdx.x >> 5, lane = threadIdx.x & 31;
    const float* a = A + (size_t)m * K;
    const float* l0 = ld + (size_t)(w * 4 + 0) * K;
    const float* l1 = l0 + K;
    const float* l2 = l1 + K;
    const float* l3 = l2 + K;
    float a0 = 0.f, a1 = 0.f, a2 = 0.f, a3 = 0.f;
    for (int k = lane; k < K; k += 32) {
        float av = a[k];
        a0 += av * l0[k]; a1 += av * l1[k]; a2 += av * l2[k]; a3 += av * l3[k];
    }
    #pragma unroll
    for (int o = 16; o; o >>= 1) {
        a0 += __shfl_xor_sync(0xffffffffu, a0, o);
        a1 += __shfl_xor_sync(0xffffffffu, a1, o);
        a2 += __shfl_xor_sync(0xffffffffu, a2, o);
        a3 += __shfl_xor_sync(0xffffffffu, a3, o);
    }
    if (!lane) {
        float* tp = t + m * RK + w * 4;
        tp[0] = f2tff(a0); tp[1] = f2tff(a1); tp[2] = f2tff(a2); tp[3] = f2tff(a3);
    }
}

// ---------------- tf32 GEMM, 3-stage cp.async ----------------
constexpr int SROW = 36;
constexpr int MAT_WORDS = 128 * SROW;       // 4608
constexpr int STAGE_WORDS = 2 * MAT_WORDS;  // 9216
constexpr int STG = 3;
constexpr int GEMM_SMEM = STG * STAGE_WORDS * 4;  // 110592

template <int EPI, int GRP>
__global__ __launch_bounds__(512) void k_gemm(const float* __restrict__ bias,
                                              float* __restrict__ Cout,
                                              int K, int N, int ldc,
                                              const float* __restrict__ xres) {
    extern __shared__ unsigned smem_u[];
    const float* A  = (EPI == 1) ? g_xmod : g_y;
    const float* TL = (EPI == 1) ? g_t1 : g_t2;
    const float* W  = (EPI == 1) ? g_w1r : g_w2r;
    const float* LU = (EPI == 1) ? g_lu1r : g_lu2r;
    float* C        = (EPI == 1) ? g_qkv : Cout;

    const int NNB = N / 128;
    int bid = blockIdx.x;
    int group = bid / (GRP * NNB);
    int within = bid - group * (GRP * NNB);
    int mb = group * GRP + (within % GRP);
    int nb = within / GRP;
    int m0 = mb << 7, n0 = nb << 7;

    int tid = threadIdx.x;
    int lane = tid & 31;
    int wid = tid >> 5;
    int wm = wid >> 2, wn = wid & 3;
    int g = lane >> 2, tg = lane & 3;

    const int KTm = K / 32;
    const int KTt = KTm + 1;   // + low-rank tile

    float acc[2][4][4];
    #pragma unroll
    for (int i = 0; i < 2; i++)
        #pragma unroll
        for (int j = 0; j < 4; j++)
            #pragma unroll
            for (int q = 0; q < 4; q++) acc[i][j][q] = 0.f;

    int c0 = tid, c1 = tid + 512;
    int ar0 = c0 >> 3, ak0 = (c0 & 7) << 2;
    int ar1 = c1 >> 3, ak1 = (c1 & 7) << 2;

    auto issue = [&](int kt, int s) {
        unsigned* sA = smem_u + s * STAGE_WORDS;
        unsigned* sB = sA + MAT_WORDS;
        const float *pA0, *pA1, *pB0, *pB1;
        if (kt < KTm) {
            const float* Ak = A + (size_t)m0 * K + kt * 32;
            const float* Wk = W + (size_t)n0 * K + kt * 32;
            pA0 = Ak + (size_t)ar0 * K + ak0;
            pA1 = Ak + (size_t)ar1 * K + ak1;
            pB0 = Wk + (size_t)ar0 * K + ak0;
            pB1 = Wk + (size_t)ar1 * K + ak1;
        } else {
            pA0 = TL + (size_t)(m0 + ar0) * RK + ak0;
            pA1 = TL + (size_t)(m0 + ar1) * RK + ak1;
            pB0 = LU + (size_t)(n0 + ar0) * RK + ak0;
            pB1 = LU + (size_t)(n0 + ar1) * RK + ak1;
        }
        cp16(sA + ar0 * SROW + ak0, pA0);
        cp16(sA + ar1 * SROW + ak1, pA1);
        cp16(sB + ar0 * SROW + ak0, pB0);
        cp16(sB + ar1 * SROW + ak1, pB1);
    };

    #pragma unroll
    for (int s = 0; s < STG - 1; s++) {
        if (s < KTt) issue(s, s);
        CP_COMMIT();
    }

    for (int kt = 0; kt < KTt; kt++) {
        int nx = kt + STG - 1;
        if (nx < KTt) issue(nx, nx % STG);
        CP_COMMIT();
        CP_WAIT(STG - 1);
        __syncthreads();
        const unsigned* sA = smem_u + (kt % STG) * STAGE_WORDS;
        const unsigned* sB = sA + MAT_WORDS;
        #pragma unroll
        for (int ks = 0; ks < 4; ks++) {
            unsigned af[2][4], bf[4][2];
            #pragma unroll
            for (int fm = 0; fm < 2; fm++) {
                int row = wm * 32 + fm * 16 + g;
                int col = ks * 8 + tg;
                af[fm][0] = sA[row * SROW + col];
                af[fm][1] = sA[(row + 8) * SROW + col];
                af[fm][2] = sA[row * SROW + col + 4];
                af[fm][3] = sA[(row + 8) * SROW + col + 4];
            }
            #pragma unroll
            for (int fn = 0; fn < 4; fn++) {
                int n = wn * 32 + fn * 8 + g;
                bf[fn][0] = sB[n * SROW + ks * 8 + tg];
                bf[fn][1] = sB[n * SROW + ks * 8 + tg + 4];
            }
            #pragma unroll
            for (int fm = 0; fm < 2; fm++)
                #pragma unroll
                for (int fn = 0; fn < 4; fn++)
                    mma8(acc[fm][fn], af[fm], bf[fn]);
        }
        __syncthreads();
    }

    #pragma unroll
    for (int fm = 0; fm < 2; fm++) {
        int r0 = m0 + wm * 32 + fm * 16 + g;
        int r1 = r0 + 8;
        #pragma unroll
        for (int fn = 0; fn < 4; fn++) {
            int cc = n0 + wn * 32 + fn * 8 + 2 * tg;
            float v0 = acc[fm][fn][0] + bias[cc];
            float v1 = acc[fm][fn][1] + bias[cc + 1];
            float v2 = acc[fm][fn][2] + bias[cc];
            float v3 = acc[fm][fn][3] + bias[cc + 1];
            if (EPI == 2) {
                float gt0 = g_mod[2 * HIDC + cc], gt1 = g_mod[2 * HIDC + cc + 1];
                v0 = xres[(size_t)r0 * ldc + cc]     + gt0 * v0;
                v1 = xres[(size_t)r0 * ldc + cc + 1] + gt1 * v1;
                v2 = xres[(size_t)r1 * ldc + cc]     + gt0 * v2;
                v3 = xres[(size_t)r1 * ldc + cc + 1] + gt1 * v3;
            }
            *(float2*)(C + (size_t)r0 * ldc + cc) = make_float2(v0, v1);
            *(float2*)(C + (size_t)r1 * ldc + cc) = make_float2(v2, v3);
        }
    }
}

// ---------------- K5: RMSNorm(q,k) + RoPE (fp32, in-place) ----------------
__global__ __launch_bounds__(128) void k_qknorm(const float* __restrict__ pe,
                                                const float* __restrict__ rqw,
                                                const float* __restrict__ rkw) {
    int l = blockIdx.x, h = blockIdx.y, d = threadIdx.x;
    size_t base = (size_t)l * NQKV + (size_t)h * 128;
    float qv = g_qkv[base + d];
    float kv = g_qkv[base + HIDC + d];
    float q2 = qv * qv, k2 = kv * kv;
    #pragma unroll
    for (int o = 16; o; o >>= 1) {
        q2 += __shfl_xor_sync(0xffffffffu, q2, o);
        k2 += __shfl_xor_sync(0xffffffffu, k2, o);
    }
    __shared__ float sq[4], sk[4];
    int w = d >> 5, lane = d & 31;
    if (!lane) { sq[w] = q2; sk[w] = k2; }
    __syncthreads();
    float Q2 = sq[0] + sq[1] + sq[2] + sq[3];
    float K2 = sk[0] + sk[1] + sk[2] + sk[3];
    float qr = rsqrtf(Q2 * (1.f / HDC) + 1e-6f);
    float kr = rsqrtf(K2 * (1.f / HDC) + 1e-6f);
    float qn = qv * qr * rqw[d];
    float kn = kv * kr * rkw[d];
    int p = d >> 1, ii = d & 1;
    const float* rot = pe + (((size_t)l * 64 + p) * 2 + ii) * 2;
    float r0 = rot[0], r1 = rot[1];
    float qo = __shfl_xor_sync(0xffffffffu, qn, 1);
    float ko = __shfl_xor_sync(0xffffffffu, kn, 1);
    float qe = ii ? qo : qn, qod = ii ? qn : qo;
    float ke = ii ? ko : kn, kod = ii ? kn : ko;
    g_qkv[base + d] = r0 * qe + r1 * qod;
    g_qkv[base + HIDC + d] = r0 * ke + r1 * kod;
}

// ---------------- K6: tensor-core flash attention ----------------
// 128q x 64k tiles, 8 warps (16 q-rows each). K split hi+lo tf32 for QK^T.
constexpr int QSs = 132, KSs = 132, VSs = 136, PSs = 68;
constexpr int OFF_KH = 128 * QSs;              // 16896
constexpr int OFF_KL = OFF_KH + 64 * KSs;      // 25344
constexpr int OFF_V  = OFF_KL + 64 * KSs;      // 33792
constexpr int OFF_P  = OFF_V + 64 * VSs;       // 42496
constexpr int ATT_WORDS = OFF_P + 128 * PSs;   // 51200
constexpr int ATT_SMEM = ATT_WORDS * 4;        // 204800

__global__ __launch_bounds__(256) void k_attn() {
    extern __shared__ unsigned sm[];
    unsigned* Qs = sm;
    unsigned* Kh = sm + OFF_KH;
    unsigned* Kl = sm + OFF_KL;
    unsigned* Vs = sm + OFF_V;
    unsigned* Ps = sm + OFF_P;

    int tid = threadIdx.x, lane = tid & 31, wid = tid >> 5;
    int g = lane >> 2, tg = lane & 3;
    int q0 = blockIdx.x * 128, h = blockIdx.y;
    size_t hb = (size_t)h * 128;
    const float scale = 0.08838834764831845f;   // 1/sqrt(128)

    // load Q tile (tf32-rounded)
    for (int i = tid; i < 128 * 32; i += 256) {
        int r = i >> 5, d4 = (i & 31) << 2;
        float4 v = *(const float4*)(g_qkv + (size_t)(q0 + r) * NQKV + hb + d4);
        uint4 u = make_uint4(f2tf(v.x), f2tf(v.y), f2tf(v.z), f2tf(v.w));
        *(uint4*)(Qs + r * QSs + d4) = u;
    }

    float m0r = -1e30f, m1r = -1e30f, l0r = 0.f, l1r = 0.f;
    float oacc[16][4];
    #pragma unroll
    for (int i = 0; i < 16; i++)
        #pragma unroll
        for (int j = 0; j < 4; j++) oacc[i][j] = 0.f;

    int arow = wid * 16 + g;

    for (int kb = 0; kb < LL / 64; kb++) {
        __syncthreads();
        int k0 = kb * 64;
        for (int i = tid; i < 64 * 32; i += 256) {
            int r = i >> 5, d4 = (i & 31) << 2;
            const float* kp = g_qkv + (size_t)(k0 + r) * NQKV + HIDC + hb + d4;
            float4 kv = *(const float4*)kp;
            unsigned h0 = f2tf(kv.x), h1 = f2tf(kv.y), h2 = f2tf(kv.z), h3 = f2tf(kv.w);
            *(uint4*)(Kh + r * KSs + d4) = make_uint4(h0, h1, h2, h3);
            uint4 lo = make_uint4(f2tf(kv.x - __uint_as_float(h0)),
                                  f2tf(kv.y - __uint_as_float(h1)),
                                  f2tf(kv.z - __uint_as_float(h2)),
                                  f2tf(kv.w - __uint_as_float(h3)));
            *(uint4*)(Kl + r * KSs + d4) = lo;
            float4 vv = *(const float4*)(kp + HIDC);
            uint4 uv = make_uint4(f2tf(vv.x), f2tf(vv.y), f2tf(vv.z), f2tf(vv.w));
            *(uint4*)(Vs + r * VSs + d4) = uv;
        }
        __syncthreads();

        // S = Q K^T (hi + lo)
        float sacc[8][4];
        #pragma unroll
        for (int i = 0; i < 8; i++)
            #pragma unroll
            for (int j = 0; j < 4; j++) sacc[i][j] = 0.f;
        #pragma unroll 4
        for (int ks = 0; ks < 16; ks++) {
            unsigned af[4];
            af[0] = Qs[arow * QSs + ks * 8 + tg];
            af[1] = Qs[(arow + 8) * QSs + ks * 8 + tg];
            af[2] = Qs[arow * QSs + ks * 8 + tg + 4];
            af[3] = Qs[(arow + 8) * QSs + ks * 8 + tg + 4];
            #pragma unroll
            for (int fn = 0; fn < 8; fn++) {
                unsigned bf[2];
                bf[0] = Kh[(fn * 8 + g) * KSs + ks * 8 + tg];
                bf[1] = Kh[(fn * 8 + g) * KSs + ks * 8 + tg + 4];
                mma8(sacc[fn], af, bf);
            }
            #pragma unroll
            for (int fn = 0; fn < 8; fn++) {
                unsigned bf[2];
                bf[0] = Kl[(fn * 8 + g) * KSs + ks * 8 + tg];
                bf[1] = Kl[(fn * 8 + g) * KSs + ks * 8 + tg + 4];
                mma8(sacc[fn], af, bf);
            }
        }

        // online softmax on fragments (rows arow, arow+8)
        float mx0 = -1e30f, mx1 = -1e30f;
        #pragma unroll
        for (int fn = 0; fn < 8; fn++) {
            sacc[fn][0] *= scale; sacc[fn][1] *= scale;
            sacc[fn][2] *= scale; sacc[fn][3] *= scale;
            mx0 = fmaxf(mx0, fmaxf(sacc[fn][0], sacc[fn][1]));
            mx1 = fmaxf(mx1, fmaxf(sacc[fn][2], sacc[fn][3]));
        }
        mx0 = fmaxf(mx0, __shfl_xor_sync(0xffffffffu, mx0, 1));
        mx0 = fmaxf(mx0, __shfl_xor_sync(0xffffffffu, mx0, 2));
        mx1 = fmaxf(mx1, __shfl_xor_sync(0xffffffffu, mx1, 1));
        mx1 = fmaxf(mx1, __shfl_xor_sync(0xffffffffu, mx1, 2));
        float mn0 = fmaxf(m0r, mx0), mn1 = fmaxf(m1r, mx1);
        float cr0 = __expf(m0r - mn0), cr1 = __expf(m1r - mn1);
        float s0 = 0.f, s1 = 0.f;
        unsigned* p0w = Ps + arow * PSs + 2 * tg;
        unsigned* p1w = Ps + (arow + 8) * PSs + 2 * tg;
        #pragma unroll
        for (int fn = 0; fn < 8; fn++) {
            float p0 = __expf(sacc[fn][0] - mn0);
            float p1 = __expf(sacc[fn][1] - mn0);
            float p2 = __expf(sacc[fn][2] - mn1);
            float p3 = __expf(sacc[fn][3] - mn1);
            s0 += p0 + p1; s1 += p2 + p3;
            p0w[fn * 8]     = f2tf(p0);
            p0w[fn * 8 + 1] = f2tf(p1);
            p1w[fn * 8]     = f2tf(p2);
            p1w[fn * 8 + 1] = f2tf(p3);
        }
        s0 += __shfl_xor_sync(0xffffffffu, s0, 1);
        s0 += __shfl_xor_sync(0xffffffffu, s0, 2);
        s1 += __shfl_xor_sync(0xffffffffu, s1, 1);
        s1 += __shfl_xor_sync(0xffffffffu, s1, 2);
        l0r = l0r * cr0 + s0;
        l1r = l1r * cr1 + s1;
        m0r = mn0; m1r = mn1;
        #pragma unroll
        for (int fn = 0; fn < 16; fn++) {
            oacc[fn][0] *= cr0; oacc[fn][1] *= cr0;
            oacc[fn][2] *= cr1; oacc[fn][3] *= cr1;
        }
        __syncwarp();

        // O += P V   (B read transposed from Vs: B[n=d][k=j] = V[j][d])
        #pragma unroll
        for (int ks = 0; ks < 8; ks++) {
            unsigned af[4];
            af[0] = Ps[arow * PSs + ks * 8 + tg];
            af[1] = Ps[(arow + 8) * PSs + ks * 8 + tg];
            af[2] = Ps[arow * PSs + ks * 8 + tg + 4];
            af[3] = Ps[(arow + 8) * PSs + ks * 8 + tg + 4];
            #pragma unroll
            for (int fn = 0; fn < 16; fn++) {
                unsigned bf[2];
                bf[0] = Vs[(ks * 8 + tg) * VSs + fn * 8 + g];
                bf[1] = Vs[(ks * 8 + tg + 4) * VSs + fn * 8 + g];
                mma8(oacc[fn], af, bf);
            }
        }
    }

    float inv0 = 1.f / l0r, inv1 = 1.f / l1r;
    int r0 = q0 + wid * 16 + g;
    #pragma unroll
    for (int fn = 0; fn < 16; fn++) {
        int c = (int)hb + fn * 8 + 2 * tg;
        float2 v0 = make_float2(f2tff(oacc[fn][0] * inv0), f2tff(oacc[fn][1] * inv0));
        float2 v1 = make_float2(f2tff(oacc[fn][2] * inv1), f2tff(oacc[fn][3] * inv1));
        *(float2*)(g_y + (size_t)r0 * NCAT + c) = v0;
        *(float2*)(g_y + (size_t)(r0 + 8) * NCAT + c) = v1;
    }
}

// ---------------- K7: gelu(tanh) -> g_y[:, 3072:] (tf32-rounded) ----------------
__global__ __launch_bounds__(256) void k_gelu() {
    int m = blockIdx.y;
    int j = blockIdx.x * 256 + threadIdx.x;
    float v = g_qkv[(size_t)m * NQKV + D3H + j];
    float t = tanhf(0.7978845608028654f * (v + 0.044715f * v * v * v));
    g_y[(size_t)m * NCAT + HIDC + j] = f2tff(0.5f * v * (1.f + t));
}

// ---------------- launch ----------------
extern "C" void kernel_launch(void* const* d_in, const int* in_sizes, int n_in,
                              void* d_out, int out_size) {
    const float* x     = (const float*)d_in[0];
    const float* vec   = (const float*)d_in[1];
    const float* pe    = (const float*)d_in[2];
    const float* mod_w = (const float*)d_in[3];
    const float* mod_b = (const float*)d_in[4];
    const float* w1    = (const float*)d_in[5];
    const float* b1    = (const float*)d_in[6];
    const float* ld1   = (const float*)d_in[7];
    const float* lu1   = (const float*)d_in[8];
    const float* w2    = (const float*)d_in[9];
    const float* b2    = (const float*)d_in[10];
    const float* ld2   = (const float*)d_in[11];
    const float* lu2   = (const float*)d_in[12];
    const float* rqw   = (const float*)d_in[13];
    const float* rkw   = (const float*)d_in[14];
    float* out = (float*)d_out;

    cudaFuncSetAttribute(k_attn, cudaFuncAttributeMaxDynamicSharedMemorySize, ATT_SMEM);
    cudaFuncSetAttribute((const void*)k_gemm<1, 12>, cudaFuncAttributeMaxDynamicSharedMemorySize, GEMM_SMEM);
    cudaFuncSetAttribute((const void*)k_gemm<2, 6>,  cudaFuncAttributeMaxDynamicSharedMemorySize, GEMM_SMEM);

    // pre-round weights to tf32
    k_round<<<(size_t)NQKV * HIDC / 1024, 256>>>(w1, 0);
    k_round<<<(size_t)HIDC * NCAT / 1024, 256>>>(w2, 1);
    k_round<<<NQKV * RK / 1024, 256>>>(lu1, 2);
    k_round<<<HIDC * RK / 1024, 256>>>(lu2, 3);

    k_mod<<<D3H / 8, 256>>>(vec, mod_w, mod_b);
    k_ln<<<LL, 256>>>(x);
    k_lowrank<<<LL, 256>>>(ld1, HIDC, 0);
    {
        int nblocks = (LL / 128) * (NQKV / 128);
        k_gemm<1, 12><<<nblocks, 512, GEMM_SMEM>>>(b1, nullptr, HIDC, NQKV, NQKV, nullptr);
    }
    {
        dim3 g(LL, NHC);
        k_qknorm<<<g, 128>>>(pe, rqw, rkw);
    }
    {
        dim3 g(LL / 128, NHC);
        k_attn<<<g, 256, ATT_SMEM>>>();
    }
    {
        dim3 g(MLPC / 256, LL);
        k_gelu<<<g, 256>>>();
    }
    k_lowrank<<<LL, 256>>>(ld2, NCAT, 1);
    {
        int nblocks = (LL / 128) * (HIDC / 128);
        k_gemm<2, 6><<<nblocks, 512, GEMM_SMEM>>>(b2, out, NCAT, HIDC, HIDC, x);
    }
}

// round 5
// speedup vs baseline: 6.4522x; 1.9107x over previous
#include <cuda_runtime.h>
#include <cuda_fp16.h>
#include <math.h>
#include <stdint.h>

// ---------------- problem constants ----------------
constexpr int LL   = 4608;
constexpr int HIDC = 3072;
constexpr int NHC  = 24;
constexpr int HDC  = 128;
constexpr int MLPC = 12288;
constexpr int RK   = 32;
constexpr int D3H  = 3 * HIDC;          // 9216
constexpr int NQKV = 3 * HIDC + MLPC;   // 21504
constexpr int NCAT = HIDC + MLPC;       // 15360

// ---------------- scratch (device globals) ----------------
__device__ float  g_mod[D3H];
__device__ float  g_qkv[(size_t)LL * NQKV];     // fp32 GEMM1 output
__device__ __half g_xmodh[(size_t)LL * HIDC];
__device__ __half g_yh[(size_t)LL * NCAT];      // attn | gelu  (fp16, GEMM2 A)
__device__ __half g_qh[(size_t)LL * HIDC];
__device__ __half g_kh[(size_t)LL * HIDC];
__device__ __half g_vh[(size_t)LL * HIDC];
__device__ __half g_t1h[LL * RK];
__device__ __half g_t2h[LL * RK];
__device__ __half g_w1h[(size_t)NQKV * HIDC];
__device__ __half g_w2h[(size_t)HIDC * NCAT];
__device__ __half g_lu1h[NQKV * RK];
__device__ __half g_lu2h[HIDC * RK];

// ---------------- asm helpers ----------------
__device__ __forceinline__ uint32_t smem_u32(const void* p) {
    uint32_t a;
    asm("{ .reg .u64 t; cvta.to.shared.u64 t, %1; cvt.u32.u64 %0, t; }" : "=r"(a) : "l"(p));
    return a;
}
__device__ __forceinline__ void cp16s(uint32_t s, const void* g) {
    asm volatile("cp.async.cg.shared.global [%0], [%1], 16;" :: "r"(s), "l"(g));
}
#define CP_COMMIT() asm volatile("cp.async.commit_group;")
#define CP_WAIT(N)  asm volatile("cp.async.wait_group %0;" :: "n"(N))

__device__ __forceinline__ void ldsm4(uint32_t* r, uint32_t a) {
    asm volatile("ldmatrix.sync.aligned.m8n8.x4.shared.b16 {%0,%1,%2,%3}, [%4];"
                 : "=r"(r[0]), "=r"(r[1]), "=r"(r[2]), "=r"(r[3]) : "r"(a));
}
__device__ __forceinline__ void ldsm4t(uint32_t* r, uint32_t a) {
    asm volatile("ldmatrix.sync.aligned.m8n8.x4.trans.shared.b16 {%0,%1,%2,%3}, [%4];"
                 : "=r"(r[0]), "=r"(r[1]), "=r"(r[2]), "=r"(r[3]) : "r"(a));
}
__device__ __forceinline__ void hmma(float* c, const uint32_t* a, const uint32_t* b) {
    asm volatile(
        "mma.sync.aligned.m16n8k16.row.col.f32.f16.f16.f32 "
        "{%0,%1,%2,%3}, {%4,%5,%6,%7}, {%8,%9}, {%0,%1,%2,%3};"
        : "+f"(c[0]), "+f"(c[1]), "+f"(c[2]), "+f"(c[3])
        : "r"(a[0]), "r"(a[1]), "r"(a[2]), "r"(a[3]), "r"(b[0]), "r"(b[1]));
}
__device__ __forceinline__ uint32_t packh2(float x, float y) {
    __half2 h = __floats2half2_rn(x, y);
    return *(uint32_t*)&h;
}

// ---------------- K0: convert weights to fp16 ----------------
__global__ __launch_bounds__(256) void k_half(const float* __restrict__ src, int which) {
    __half* dst = which == 0 ? g_w1h : which == 1 ? g_w2h : which == 2 ? g_lu1h : g_lu2h;
    size_t i = ((size_t)blockIdx.x * 256 + threadIdx.x) * 8;
    float4 v0 = *(const float4*)(src + i);
    float4 v1 = *(const float4*)(src + i + 4);
    __half2 h[4];
    h[0] = __floats2half2_rn(v0.x, v0.y);
    h[1] = __floats2half2_rn(v0.z, v0.w);
    h[2] = __floats2half2_rn(v1.x, v1.y);
    h[3] = __floats2half2_rn(v1.z, v1.w);
    *(uint4*)(dst + i) = *(uint4*)h;
}

// ---------------- K1: mod = silu(vec) @ mod_w^T + mod_b ----------------
__global__ __launch_bounds__(256) void k_mod(const float* __restrict__ vec,
                                             const float* __restrict__ mod_w,
                                             const float* __restrict__ mod_b) {
    int j = blockIdx.x * 8 + (threadIdx.x >> 5);
    int lane = threadIdx.x & 31;
    if (j >= D3H) return;
    const float* wr = mod_w + (size_t)j * HIDC;
    float acc = 0.f;
    for (int k = lane; k < HIDC; k += 32) {
        float s = vec[k];
        acc += (s / (1.f + expf(-s))) * wr[k];
    }
    #pragma unroll
    for (int o = 16; o; o >>= 1) acc += __shfl_xor_sync(0xffffffffu, acc, o);
    if (lane == 0) g_mod[j] = acc + mod_b[j];
}

// ---------------- K2: LayerNorm + modulation -> g_xmodh (fp16) ----------------
__global__ __launch_bounds__(256) void k_ln(const float* __restrict__ x) {
    __shared__ float rs[8], rs2[8];
    int m = blockIdx.x;
    const float* row = x + (size_t)m * HIDC;
    float v[12];
    float s = 0.f, s2 = 0.f;
    #pragma unroll
    for (int i = 0; i < 12; i++) {
        v[i] = row[threadIdx.x + i * 256];
        s += v[i]; s2 += v[i] * v[i];
    }
    int lane = threadIdx.x & 31, w = threadIdx.x >> 5;
    #pragma unroll
    for (int o = 16; o; o >>= 1) {
        s  += __shfl_xor_sync(0xffffffffu, s, o);
        s2 += __shfl_xor_sync(0xffffffffu, s2, o);
    }
    if (!lane) { rs[w] = s; rs2[w] = s2; }
    __syncthreads();
    float S = 0.f, S2 = 0.f;
    #pragma unroll
    for (int i = 0; i < 8; i++) { S += rs[i]; S2 += rs2[i]; }
    float mu = S * (1.f / HIDC);
    float var = S2 * (1.f / HIDC) - mu * mu;
    float rstd = rsqrtf(var + 1e-6f);
    __half* orow = g_xmodh + (size_t)m * HIDC;
    #pragma unroll
    for (int i = 0; i < 12; i++) {
        int c = threadIdx.x + i * 256;
        float xn = (v[i] - mu) * rstd;
        orow[c] = __float2half_rn(xn * (1.f + g_mod[HIDC + c]) + g_mod[c]);
    }
}

// ---------------- K3/K8: low-rank projector t = A @ ld^T ----------------
__global__ __launch_bounds__(256) void k_lowrank(const float* __restrict__ ld, int K, int sel) {
    const __half* A = sel ? g_yh : g_xmodh;
    __half* t = sel ? g_t2h : g_t1h;
    int m = blockIdx.x;
    int w = threadIdx.x >> 5, lane = threadIdx.x & 31;
    const __half* a = A + (size_t)m * K;
    const float* l0 = ld + (size_t)(w * 4 + 0) * K;
    const float* l1 = l0 + K;
    const float* l2 = l1 + K;
    const float* l3 = l2 + K;
    float a0 = 0.f, a1 = 0.f, a2 = 0.f, a3 = 0.f;
    for (int k = lane; k < K; k += 32) {
        float av = __half2float(a[k]);
        a0 += av * l0[k]; a1 += av * l1[k]; a2 += av * l2[k]; a3 += av * l3[k];
    }
    #pragma unroll
    for (int o = 16; o; o >>= 1) {
        a0 += __shfl_xor_sync(0xffffffffu, a0, o);
        a1 += __shfl_xor_sync(0xffffffffu, a1, o);
        a2 += __shfl_xor_sync(0xffffffffu, a2, o);
        a3 += __shfl_xor_sync(0xffffffffu, a3, o);
    }
    if (!lane) {
        __half* tp = t + m * RK + w * 4;
        tp[0] = __float2half_rn(a0); tp[1] = __float2half_rn(a1);
        tp[2] = __float2half_rn(a2); tp[3] = __float2half_rn(a3);
    }
}

// ---------------- fp16 mma GEMM: 128x128 tile, 256 thr, 4-stage cp.async ----------------
constexpr int HST = 40;                           // halves per smem row (32 data + 8 pad)
constexpr int TILE_H = 128 * HST;                 // halves per matrix tile
constexpr int STAGE_H = 2 * TILE_H;
constexpr int STG = 4;
constexpr int GEMM_SMEM = STG * STAGE_H * 2;      // 81920 B

template <int EPI, int GRP>
__global__ __launch_bounds__(256, 2) void k_gemm(const float* __restrict__ bias,
                                                 float* __restrict__ Cout,
                                                 int K, int N, int ldc,
                                                 const float* __restrict__ xres) {
    extern __shared__ __half smh[];
    uint32_t sb = smem_u32(smh);
    const __half* A  = (EPI == 1) ? g_xmodh : g_yh;
    const __half* TL = (EPI == 1) ? g_t1h : g_t2h;
    const __half* W  = (EPI == 1) ? g_w1h : g_w2h;
    const __half* LU = (EPI == 1) ? g_lu1h : g_lu2h;
    float* C         = (EPI == 1) ? g_qkv : Cout;

    const int NNB = N / 128;
    int bid = blockIdx.x;
    int group = bid / (GRP * NNB);
    int within = bid - group * (GRP * NNB);
    int mb = group * GRP + (within % GRP);
    int nb = within / GRP;
    int m0 = mb << 7, n0 = nb << 7;

    int tid = threadIdx.x, lane = tid & 31, wid = tid >> 5;
    int wm = wid >> 1, wn = wid & 1;               // 4x2 warp grid, warptile 32x64

    const int KTm = K / 32;
    const int KT = KTm + 1;                        // + low-rank tile

    float acc[2][8][4];
    #pragma unroll
    for (int i = 0; i < 2; i++)
        #pragma unroll
        for (int j = 0; j < 8; j++)
            #pragma unroll
            for (int q = 0; q < 4; q++) acc[i][j][q] = 0.f;

    int ch = tid & 3;            // 16B chunk within row (0..3)
    int rb = tid >> 2;           // row base (0..63)

    auto issue = [&](int kt) {
        int s = kt & (STG - 1);
        uint32_t base = sb + s * STAGE_H * 2;
        bool mn = kt < KTm;
        #pragma unroll
        for (int j = 0; j < 4; j++) {
            int mat = j >> 1;                      // 0: A, 1: B
            int r = rb + (j & 1) * 64;
            uint32_t dst = base + (uint32_t)(mat * TILE_H + r * HST + ch * 8) * 2;
            const __half* src;
            if (mat == 0)
                src = mn ? A + (size_t)(m0 + r) * K + kt * 32 + ch * 8
                         : TL + (size_t)(m0 + r) * RK + ch * 8;
            else
                src = mn ? W + (size_t)(n0 + r) * K + kt * 32 + ch * 8
                         : LU + (size_t)(n0 + r) * RK + ch * 8;
            cp16s(dst, src);
        }
    };

    #pragma unroll
    for (int s = 0; s < STG - 1; s++) { issue(s); CP_COMMIT(); }

    for (int kt = 0; kt < KT; kt++) {
        int nx = kt + STG - 1;
        if (nx < KT) issue(nx);
        CP_COMMIT();
        CP_WAIT(STG - 1);
        __syncthreads();
        uint32_t sA = sb + (uint32_t)(kt & (STG - 1)) * STAGE_H * 2;
        uint32_t sB = sA + TILE_H * 2;
        #pragma unroll
        for (int ks = 0; ks < 2; ks++) {
            uint32_t af[2][4];
            #pragma unroll
            for (int fm = 0; fm < 2; fm++) {
                int r = wm * 32 + fm * 16 + (lane & 15);
                int kc = ks * 16 + (lane >> 4) * 8;
                ldsm4(af[fm], sA + (uint32_t)(r * HST + kc) * 2);
            }
            uint32_t bf[4][4];
            #pragma unroll
            for (int fp = 0; fp < 4; fp++) {
                int nr = wn * 64 + fp * 16 + (lane & 7) + ((lane >> 4) & 1) * 8;
                int kc = ks * 16 + ((lane >> 3) & 1) * 8;
                ldsm4(bf[fp], sB + (uint32_t)(nr * HST + kc) * 2);
            }
            #pragma unroll
            for (int fm = 0; fm < 2; fm++)
                #pragma unroll
                for (int fn = 0; fn < 8; fn++)
                    hmma(acc[fm][fn], af[fm], &bf[fn >> 1][(fn & 1) * 2]);
        }
        __syncthreads();
    }

    // epilogue
    int g = lane >> 2, tg = lane & 3;
    #pragma unroll
    for (int fm = 0; fm < 2; fm++) {
        int r0 = m0 + wm * 32 + fm * 16 + g;
        int r1 = r0 + 8;
        #pragma unroll
        for (int fn = 0; fn < 8; fn++) {
            int cc = n0 + wn * 64 + fn * 8 + 2 * tg;
            float v0 = acc[fm][fn][0] + bias[cc];
            float v1 = acc[fm][fn][1] + bias[cc + 1];
            float v2 = acc[fm][fn][2] + bias[cc];
            float v3 = acc[fm][fn][3] + bias[cc + 1];
            if (EPI == 2) {
                float gt0 = g_mod[2 * HIDC + cc], gt1 = g_mod[2 * HIDC + cc + 1];
                v0 = xres[(size_t)r0 * ldc + cc]     + gt0 * v0;
                v1 = xres[(size_t)r0 * ldc + cc + 1] + gt1 * v1;
                v2 = xres[(size_t)r1 * ldc + cc]     + gt0 * v2;
                v3 = xres[(size_t)r1 * ldc + cc + 1] + gt1 * v3;
            }
            *(float2*)(C + (size_t)r0 * ldc + cc) = make_float2(v0, v1);
            *(float2*)(C + (size_t)r1 * ldc + cc) = make_float2(v2, v3);
        }
    }
}

// ---------------- K5: RMSNorm(q,k) + RoPE -> fp16 q/k/v ----------------
__global__ __launch_bounds__(128) void k_qknorm(const float* __restrict__ pe,
                                                const float* __restrict__ rqw,
                                                const float* __restrict__ rkw) {
    int l = blockIdx.x, h = blockIdx.y, d = threadIdx.x;
    size_t base = (size_t)l * NQKV + (size_t)h * 128;
    float qv = g_qkv[base + d];
    float kv = g_qkv[base + HIDC + d];
    float vv = g_qkv[base + 2 * HIDC + d];
    float q2 = qv * qv, k2 = kv * kv;
    #pragma unroll
    for (int o = 16; o; o >>= 1) {
        q2 += __shfl_xor_sync(0xffffffffu, q2, o);
        k2 += __shfl_xor_sync(0xffffffffu, k2, o);
    }
    __shared__ float sq[4], sk[4];
    int w = d >> 5, lane = d & 31;
    if (!lane) { sq[w] = q2; sk[w] = k2; }
    __syncthreads();
    float Q2 = sq[0] + sq[1] + sq[2] + sq[3];
    float K2 = sk[0] + sk[1] + sk[2] + sk[3];
    float qr = rsqrtf(Q2 * (1.f / HDC) + 1e-6f);
    float kr = rsqrtf(K2 * (1.f / HDC) + 1e-6f);
    float qn = qv * qr * rqw[d];
    float kn = kv * kr * rkw[d];
    int p = d >> 1, ii = d & 1;
    const float* rot = pe + (((size_t)l * 64 + p) * 2 + ii) * 2;
    float r0 = rot[0], r1 = rot[1];
    float qo = __shfl_xor_sync(0xffffffffu, qn, 1);
    float ko = __shfl_xor_sync(0xffffffffu, kn, 1);
    float qe = ii ? qo : qn, qod = ii ? qn : qo;
    float ke = ii ? ko : kn, kod = ii ? kn : ko;
    size_t ob = (size_t)l * HIDC + (size_t)h * 128 + d;
    g_qh[ob] = __float2half_rn(r0 * qe + r1 * qod);
    g_kh[ob] = __float2half_rn(r0 * ke + r1 * kod);
    g_vh[ob] = __float2half_rn(vv);
}

// ---------------- K6: fp16 tensor-core flash attention ----------------
// 128q x 64k tiles, 8 warps, P in registers, V via ldmatrix.trans
constexpr int AST = 136;                       // halves per smem row
constexpr int OQ = 0;
constexpr int OK = 128 * AST;                  // 17408
constexpr int OV = OK + 64 * AST;              // 26112
constexpr int ATT_H = OV + 64 * AST;           // 34816 halves
constexpr int ATT_SMEM = ATT_H * 2;            // 69632 B

__global__ __launch_bounds__(256) void k_attn() {
    extern __shared__ __half smh[];
    uint32_t sb = smem_u32(smh);

    int tid = threadIdx.x, lane = tid & 31, wid = tid >> 5;
    int g = lane >> 2, tg = lane & 3;
    int q0 = blockIdx.x * 128, h = blockIdx.y;
    size_t hb = (size_t)h * 128;
    const float scale = 0.08838834764831845f;

    // load Q tile (uint4 = 8 halves)
    for (int i = tid; i < 128 * 16; i += 256) {
        int r = i >> 4, c = (i & 15) * 8;
        *(uint4*)(smh + OQ + r * AST + c) =
            *(const uint4*)(g_qh + (size_t)(q0 + r) * HIDC + hb + c);
    }

    float m0r = -1e30f, m1r = -1e30f, l0r = 0.f, l1r = 0.f;
    float oacc[16][4];
    #pragma unroll
    for (int i = 0; i < 16; i++)
        #pragma unroll
        for (int j = 0; j < 4; j++) oacc[i][j] = 0.f;

    for (int kb = 0; kb < LL / 64; kb++) {
        __syncthreads();
        int k0 = kb * 64;
        for (int i = tid; i < 64 * 16; i += 256) {
            int r = i >> 4, c = (i & 15) * 8;
            *(uint4*)(smh + OK + r * AST + c) =
                *(const uint4*)(g_kh + (size_t)(k0 + r) * HIDC + hb + c);
            *(uint4*)(smh + OV + r * AST + c) =
                *(const uint4*)(g_vh + (size_t)(k0 + r) * HIDC + hb + c);
        }
        __syncthreads();

        // S = Q K^T
        float sacc[8][4];
        #pragma unroll
        for (int i = 0; i < 8; i++)
            #pragma unroll
            for (int j = 0; j < 4; j++) sacc[i][j] = 0.f;
        #pragma unroll
        for (int ks = 0; ks < 8; ks++) {
            uint32_t af[4];
            {
                int r = wid * 16 + (lane & 15);
                int kc = ks * 16 + (lane >> 4) * 8;
                ldsm4(af, sb + (uint32_t)(OQ + r * AST + kc) * 2);
            }
            #pragma unroll
            for (int fp = 0; fp < 4; fp++) {
                uint32_t bf[4];
                int nr = fp * 16 + (lane & 7) + ((lane >> 4) & 1) * 8;
                int kc = ks * 16 + ((lane >> 3) & 1) * 8;
                ldsm4(bf, sb + (uint32_t)(OK + nr * AST + kc) * 2);
                hmma(sacc[2 * fp], af, &bf[0]);
                hmma(sacc[2 * fp + 1], af, &bf[2]);
            }
        }

        // online softmax (rows g and g+8 of this warp's 16 rows)
        float mx0 = -1e30f, mx1 = -1e30f;
        #pragma unroll
        for (int fn = 0; fn < 8; fn++) {
            sacc[fn][0] *= scale; sacc[fn][1] *= scale;
            sacc[fn][2] *= scale; sacc[fn][3] *= scale;
            mx0 = fmaxf(mx0, fmaxf(sacc[fn][0], sacc[fn][1]));
            mx1 = fmaxf(mx1, fmaxf(sacc[fn][2], sacc[fn][3]));
        }
        mx0 = fmaxf(mx0, __shfl_xor_sync(0xffffffffu, mx0, 1));
        mx0 = fmaxf(mx0, __shfl_xor_sync(0xffffffffu, mx0, 2));
        mx1 = fmaxf(mx1, __shfl_xor_sync(0xffffffffu, mx1, 1));
        mx1 = fmaxf(mx1, __shfl_xor_sync(0xffffffffu, mx1, 2));
        float mn0 = fmaxf(m0r, mx0), mn1 = fmaxf(m1r, mx1);
        float cr0 = __expf(m0r - mn0), cr1 = __expf(m1r - mn1);
        float s0 = 0.f, s1 = 0.f;
        #pragma unroll
        for (int fn = 0; fn < 8; fn++) {
            sacc[fn][0] = __expf(sacc[fn][0] - mn0);
            sacc[fn][1] = __expf(sacc[fn][1] - mn0);
            sacc[fn][2] = __expf(sacc[fn][2] - mn1);
            sacc[fn][3] = __expf(sacc[fn][3] - mn1);
            s0 += sacc[fn][0] + sacc[fn][1];
            s1 += sacc[fn][2] + sacc[fn][3];
        }
        s0 += __shfl_xor_sync(0xffffffffu, s0, 1);
        s0 += __shfl_xor_sync(0xffffffffu, s0, 2);
        s1 += __shfl_xor_sync(0xffffffffu, s1, 1);
        s1 += __shfl_xor_sync(0xffffffffu, s1, 2);
        l0r = l0r * cr0 + s0;
        l1r = l1r * cr1 + s1;
        m0r = mn0; m1r = mn1;
        #pragma unroll
        for (int fn = 0; fn < 16; fn++) {
            oacc[fn][0] *= cr0; oacc[fn][1] *= cr0;
            oacc[fn][2] *= cr1; oacc[fn][3] *= cr1;
        }

        // O += P V  (P packed from registers; V B-frags via ldmatrix.trans)
        #pragma unroll
        for (int ks = 0; ks < 4; ks++) {
            uint32_t pa[4];
            pa[0] = packh2(sacc[2 * ks][0],     sacc[2 * ks][1]);
            pa[1] = packh2(sacc[2 * ks][2],     sacc[2 * ks][3]);
            pa[2] = packh2(sacc[2 * ks + 1][0], sacc[2 * ks + 1][1]);
            pa[3] = packh2(sacc[2 * ks + 1][2], sacc[2 * ks + 1][3]);
            #pragma unroll
            for (int fp = 0; fp < 8; fp++) {
                uint32_t bf[4];
                int kr = ks * 16 + (lane & 7) + ((lane >> 3) & 1) * 8;
                int dc = fp * 16 + (lane >> 4) * 8;
                ldsm4t(bf, sb + (uint32_t)(OV + kr * AST + dc) * 2);
                hmma(oacc[2 * fp], pa, &bf[0]);
                hmma(oacc[2 * fp + 1], pa, &bf[2]);
            }
        }
    }

    float inv0 = 1.f / l0r, inv1 = 1.f / l1r;
    int r0 = q0 + wid * 16 + g;
    #pragma unroll
    for (int fn = 0; fn < 16; fn++) {
        int c = (int)hb + fn * 8 + 2 * tg;
        *(__half2*)(g_yh + (size_t)r0 * NCAT + c) =
            __floats2half2_rn(oacc[fn][0] * inv0, oacc[fn][1] * inv0);
        *(__half2*)(g_yh + (size_t)(r0 + 8) * NCAT + c) =
            __floats2half2_rn(oacc[fn][2] * inv1, oacc[fn][3] * inv1);
    }
}

// ---------------- K7: gelu(tanh) -> g_yh[:, 3072:] (fp16) ----------------
__global__ __launch_bounds__(256) void k_gelu() {
    int m = blockIdx.y;
    int j = blockIdx.x * 256 + threadIdx.x;
    float v = g_qkv[(size_t)m * NQKV + D3H + j];
    float t = tanhf(0.7978845608028654f * (v + 0.044715f * v * v * v));
    g_yh[(size_t)m * NCAT + HIDC + j] = __float2half_rn(0.5f * v * (1.f + t));
}

// ---------------- launch ----------------
extern "C" void kernel_launch(void* const* d_in, const int* in_sizes, int n_in,
                              void* d_out, int out_size) {
    const float* x     = (const float*)d_in[0];
    const float* vec   = (const float*)d_in[1];
    const float* pe    = (const float*)d_in[2];
    const float* mod_w = (const float*)d_in[3];
    const float* mod_b = (const float*)d_in[4];
    const float* w1    = (const float*)d_in[5];
    const float* b1    = (const float*)d_in[6];
    const float* ld1   = (const float*)d_in[7];
    const float* lu1   = (const float*)d_in[8];
    const float* w2    = (const float*)d_in[9];
    const float* b2    = (const float*)d_in[10];
    const float* ld2   = (const float*)d_in[11];
    const float* lu2   = (const float*)d_in[12];
    const float* rqw   = (const float*)d_in[13];
    const float* rkw   = (const float*)d_in[14];
    float* out = (float*)d_out;

    cudaFuncSetAttribute(k_attn, cudaFuncAttributeMaxDynamicSharedMemorySize, ATT_SMEM);
    cudaFuncSetAttribute((const void*)k_gemm<1, 12>, cudaFuncAttributeMaxDynamicSharedMemorySize, GEMM_SMEM);
    cudaFuncSetAttribute((const void*)k_gemm<2, 6>,  cudaFuncAttributeMaxDynamicSharedMemorySize, GEMM_SMEM);

    // convert weights to fp16
    k_half<<<(int)((size_t)NQKV * HIDC / 2048), 256>>>(w1, 0);
    k_half<<<(int)((size_t)HIDC * NCAT / 2048), 256>>>(w2, 1);
    k_half<<<NQKV * RK / 2048, 256>>>(lu1, 2);
    k_half<<<HIDC * RK / 2048, 256>>>(lu2, 3);

    k_mod<<<D3H / 8, 256>>>(vec, mod_w, mod_b);
    k_ln<<<LL, 256>>>(x);
    k_lowrank<<<LL, 256>>>(ld1, HIDC, 0);
    {
        int nblocks = (LL / 128) * (NQKV / 128);   // 36 * 168
        k_gemm<1, 12><<<nblocks, 256, GEMM_SMEM>>>(b1, nullptr, HIDC, NQKV, NQKV, nullptr);
    }
    {
        dim3 gq(LL, NHC);
        k_qknorm<<<gq, 128>>>(pe, rqw, rkw);
    }
    {
        dim3 ga(LL / 128, NHC);
        k_attn<<<ga, 256, ATT_SMEM>>>();
    }
    {
        dim3 gg(MLPC / 256, LL);
        k_gelu<<<gg, 256>>>();
    }
    k_lowrank<<<LL, 256>>>(ld2, NCAT, 1);
    {
        int nblocks = (LL / 128) * (HIDC / 128);   // 36 * 24
        k_gemm<2, 6><<<nblocks, 256, GEMM_SMEM>>>(b2, out, NCAT, HIDC, HIDC, x);
    }
}

// round 6
// speedup vs baseline: 6.8641x; 1.0639x over previous
#include <cuda_runtime.h>
#include <cuda_fp16.h>
#include <math.h>
#include <stdint.h>

// ---------------- problem constants ----------------
constexpr int LL   = 4608;
constexpr int HIDC = 3072;
constexpr int NHC  = 24;
constexpr int HDC  = 128;
constexpr int MLPC = 12288;
constexpr int RK   = 32;
constexpr int D3H  = 3 * HIDC;          // 9216
constexpr int NQKV = 3 * HIDC + MLPC;   // 21504
constexpr int NCAT = HIDC + MLPC;       // 15360

// ---------------- scratch (device globals) ----------------
__device__ float  g_mod[D3H];
__device__ __half g_xmodh[(size_t)LL * HIDC];
__device__ __half g_yh[(size_t)LL * NCAT];      // attn | gelu(mlp)  (GEMM2 A)
__device__ __half g_qh[(size_t)LL * HIDC];
__device__ __half g_kh[(size_t)LL * HIDC];
__device__ __half g_vh[(size_t)LL * HIDC];
__device__ __half g_t1h[LL * RK];
__device__ __half g_t2h[LL * RK];
__device__ __half g_w1h[(size_t)NQKV * HIDC];
__device__ __half g_w2h[(size_t)HIDC * NCAT];
__device__ __half g_lu1h[NQKV * RK];
__device__ __half g_lu2h[HIDC * RK];

// ---------------- asm helpers ----------------
__device__ __forceinline__ uint32_t smem_u32(const void* p) {
    uint32_t a;
    asm("{ .reg .u64 t; cvta.to.shared.u64 t, %1; cvt.u32.u64 %0, t; }" : "=r"(a) : "l"(p));
    return a;
}
__device__ __forceinline__ void cp16s(uint32_t s, const void* g) {
    asm volatile("cp.async.cg.shared.global [%0], [%1], 16;" :: "r"(s), "l"(g));
}
#define CP_COMMIT() asm volatile("cp.async.commit_group;")
#define CP_WAIT(N)  asm volatile("cp.async.wait_group %0;" :: "n"(N))

__device__ __forceinline__ void ldsm4(uint32_t* r, uint32_t a) {
    asm volatile("ldmatrix.sync.aligned.m8n8.x4.shared.b16 {%0,%1,%2,%3}, [%4];"
                 : "=r"(r[0]), "=r"(r[1]), "=r"(r[2]), "=r"(r[3]) : "r"(a));
}
__device__ __forceinline__ void ldsm4t(uint32_t* r, uint32_t a) {
    asm volatile("ldmatrix.sync.aligned.m8n8.x4.trans.shared.b16 {%0,%1,%2,%3}, [%4];"
                 : "=r"(r[0]), "=r"(r[1]), "=r"(r[2]), "=r"(r[3]) : "r"(a));
}
__device__ __forceinline__ void hmma(float* c, const uint32_t* a, const uint32_t* b) {
    asm volatile(
        "mma.sync.aligned.m16n8k16.row.col.f32.f16.f16.f32 "
        "{%0,%1,%2,%3}, {%4,%5,%6,%7}, {%8,%9}, {%0,%1,%2,%3};"
        : "+f"(c[0]), "+f"(c[1]), "+f"(c[2]), "+f"(c[3])
        : "r"(a[0]), "r"(a[1]), "r"(a[2]), "r"(a[3]), "r"(b[0]), "r"(b[1]));
}
__device__ __forceinline__ uint32_t packh2(float x, float y) {
    __half2 h = __floats2half2_rn(x, y);
    return *(uint32_t*)&h;
}
__device__ __forceinline__ float gelu_f(float v) {
    float u = 0.7978845608028654f * (v + 0.044715f * v * v * v);
    float t = 1.f - 2.f / (__expf(2.f * u) + 1.f);
    return 0.5f * v * (1.f + t);
}

// ---------------- K0: convert weights to fp16 ----------------
__global__ __launch_bounds__(256) void k_half(const float* __restrict__ src, int which) {
    __half* dst = which == 0 ? g_w1h : which == 1 ? g_w2h : which == 2 ? g_lu1h : g_lu2h;
    size_t i = ((size_t)blockIdx.x * 256 + threadIdx.x) * 8;
    float4 v0 = *(const float4*)(src + i);
    float4 v1 = *(const float4*)(src + i + 4);
    __half2 h[4];
    h[0] = __floats2half2_rn(v0.x, v0.y);
    h[1] = __floats2half2_rn(v0.z, v0.w);
    h[2] = __floats2half2_rn(v1.x, v1.y);
    h[3] = __floats2half2_rn(v1.z, v1.w);
    *(uint4*)(dst + i) = *(uint4*)h;
}

// ---------------- K1: mod = silu(vec) @ mod_w^T + mod_b ----------------
__global__ __launch_bounds__(256) void k_mod(const float* __restrict__ vec,
                                             const float* __restrict__ mod_w,
                                             const float* __restrict__ mod_b) {
    int j = blockIdx.x * 8 + (threadIdx.x >> 5);
    int lane = threadIdx.x & 31;
    if (j >= D3H) return;
    const float* wr = mod_w + (size_t)j * HIDC;
    float acc = 0.f;
    for (int k = lane; k < HIDC; k += 32) {
        float s = vec[k];
        acc += (s / (1.f + expf(-s))) * wr[k];
    }
    #pragma unroll
    for (int o = 16; o; o >>= 1) acc += __shfl_xor_sync(0xffffffffu, acc, o);
    if (lane == 0) g_mod[j] = acc + mod_b[j];
}

// ---------------- K2: LayerNorm + modulation -> g_xmodh (fp16) ----------------
__global__ __launch_bounds__(256) void k_ln(const float* __restrict__ x) {
    __shared__ float rs[8], rs2[8];
    int m = blockIdx.x;
    const float* row = x + (size_t)m * HIDC;
    float v[12];
    float s = 0.f, s2 = 0.f;
    #pragma unroll
    for (int i = 0; i < 12; i++) {
        v[i] = row[threadIdx.x + i * 256];
        s += v[i]; s2 += v[i] * v[i];
    }
    int lane = threadIdx.x & 31, w = threadIdx.x >> 5;
    #pragma unroll
    for (int o = 16; o; o >>= 1) {
        s  += __shfl_xor_sync(0xffffffffu, s, o);
        s2 += __shfl_xor_sync(0xffffffffu, s2, o);
    }
    if (!lane) { rs[w] = s; rs2[w] = s2; }
    __syncthreads();
    float S = 0.f, S2 = 0.f;
    #pragma unroll
    for (int i = 0; i < 8; i++) { S += rs[i]; S2 += rs2[i]; }
    float mu = S * (1.f / HIDC);
    float var = S2 * (1.f / HIDC) - mu * mu;
    float rstd = rsqrtf(var + 1e-6f);
    __half* orow = g_xmodh + (size_t)m * HIDC;
    #pragma unroll
    for (int i = 0; i < 12; i++) {
        int c = threadIdx.x + i * 256;
        float xn = (v[i] - mu) * rstd;
        orow[c] = __float2half_rn(xn * (1.f + g_mod[HIDC + c]) + g_mod[c]);
    }
}

// ---------------- K3/K8: low-rank projector t = A @ ld^T (vectorized) ----------------
__global__ __launch_bounds__(256) void k_lowrank(const float* __restrict__ ld, int K, int sel) {
    const __half* A = sel ? g_yh : g_xmodh;
    __half* t = sel ? g_t2h : g_t1h;
    int m = blockIdx.x;
    int w = threadIdx.x >> 5, lane = threadIdx.x & 31;
    const __half* a = A + (size_t)m * K;
    const float* lrow[4];
    #pragma unroll
    for (int r = 0; r < 4; r++) lrow[r] = ld + (size_t)(w * 4 + r) * K;
    float acc4[4] = {0.f, 0.f, 0.f, 0.f};
    for (int k = lane * 8; k < K; k += 256) {
        uint4 av_u = *(const uint4*)(a + k);
        const __half2* ah = (const __half2*)&av_u;
        float2 af[4];
        #pragma unroll
        for (int i = 0; i < 4; i++) af[i] = __half22float2(ah[i]);
        #pragma unroll
        for (int r = 0; r < 4; r++) {
            float4 l0 = *(const float4*)(lrow[r] + k);
            float4 l1 = *(const float4*)(lrow[r] + k + 4);
            acc4[r] += af[0].x * l0.x + af[0].y * l0.y + af[1].x * l0.z + af[1].y * l0.w
                     + af[2].x * l1.x + af[2].y * l1.y + af[3].x * l1.z + af[3].y * l1.w;
        }
    }
    #pragma unroll
    for (int o = 16; o; o >>= 1) {
        #pragma unroll
        for (int r = 0; r < 4; r++)
            acc4[r] += __shfl_xor_sync(0xffffffffu, acc4[r], o);
    }
    if (!lane) {
        __half* tp = t + m * RK + w * 4;
        #pragma unroll
        for (int r = 0; r < 4; r++) tp[r] = __float2half_rn(acc4[r]);
    }
}

// ---------------- fp16 mma GEMM: 128x128 tile, 256 thr, 4-stage cp.async ----------------
constexpr int HST = 40;
constexpr int TILE_H = 128 * HST;
constexpr int STAGE_H = 2 * TILE_H;
constexpr int STG = 4;
constexpr int GEMM_SMEM = STG * STAGE_H * 2;      // 81920 B

// EPI==1: A=g_xmodh, fused epilogue -> fp16 q/k/v/gelu(mlp)
// EPI==2: A=g_yh, out = x + gate*(acc+bias) fp32
template <int EPI, int GRP>
__global__ __launch_bounds__(256, 2) void k_gemm(const float* __restrict__ bias,
                                                 float* __restrict__ Cout,
                                                 int K, int N, int ldc,
                                                 const float* __restrict__ xres) {
    extern __shared__ __half smh[];
    uint32_t sb = smem_u32(smh);
    const __half* A  = (EPI == 1) ? g_xmodh : g_yh;
    const __half* TL = (EPI == 1) ? g_t1h : g_t2h;
    const __half* W  = (EPI == 1) ? g_w1h : g_w2h;
    const __half* LU = (EPI == 1) ? g_lu1h : g_lu2h;

    const int NNB = N / 128;
    int bid = blockIdx.x;
    int group = bid / (GRP * NNB);
    int within = bid - group * (GRP * NNB);
    int mb = group * GRP + (within % GRP);
    int nb = within / GRP;
    int m0 = mb << 7, n0 = nb << 7;

    int tid = threadIdx.x, lane = tid & 31, wid = tid >> 5;
    int wm = wid >> 1, wn = wid & 1;               // 4x2 warp grid, warptile 32x64

    const int KTm = K / 32;
    const int KT = KTm + 1;                        // + low-rank tile

    float acc[2][8][4];
    #pragma unroll
    for (int i = 0; i < 2; i++)
        #pragma unroll
        for (int j = 0; j < 8; j++)
            #pragma unroll
            for (int q = 0; q < 4; q++) acc[i][j][q] = 0.f;

    int ch = tid & 3;
    int rb = tid >> 2;

    auto issue = [&](int kt) {
        int s = kt & (STG - 1);
        uint32_t base = sb + s * STAGE_H * 2;
        bool mn = kt < KTm;
        #pragma unroll
        for (int j = 0; j < 4; j++) {
            int mat = j >> 1;
            int r = rb + (j & 1) * 64;
            uint32_t dst = base + (uint32_t)(mat * TILE_H + r * HST + ch * 8) * 2;
            const __half* src;
            if (mat == 0)
                src = mn ? A + (size_t)(m0 + r) * K + kt * 32 + ch * 8
                         : TL + (size_t)(m0 + r) * RK + ch * 8;
            else
                src = mn ? W + (size_t)(n0 + r) * K + kt * 32 + ch * 8
                         : LU + (size_t)(n0 + r) * RK + ch * 8;
            cp16s(dst, src);
        }
    };

    #pragma unroll
    for (int s = 0; s < STG - 1; s++) { issue(s); CP_COMMIT(); }

    for (int kt = 0; kt < KT; kt++) {
        int nx = kt + STG - 1;
        if (nx < KT) issue(nx);
        CP_COMMIT();
        CP_WAIT(STG - 1);
        __syncthreads();
        uint32_t sA = sb + (uint32_t)(kt & (STG - 1)) * STAGE_H * 2;
        uint32_t sB = sA + TILE_H * 2;
        #pragma unroll
        for (int ks = 0; ks < 2; ks++) {
            uint32_t af[2][4];
            #pragma unroll
            for (int fm = 0; fm < 2; fm++) {
                int r = wm * 32 + fm * 16 + (lane & 15);
                int kc = ks * 16 + (lane >> 4) * 8;
                ldsm4(af[fm], sA + (uint32_t)(r * HST + kc) * 2);
            }
            uint32_t bf[4][4];
            #pragma unroll
            for (int fp = 0; fp < 4; fp++) {
                int nr = wn * 64 + fp * 16 + (lane & 7) + ((lane >> 4) & 1) * 8;
                int kc = ks * 16 + ((lane >> 3) & 1) * 8;
                ldsm4(bf[fp], sB + (uint32_t)(nr * HST + kc) * 2);
            }
            #pragma unroll
            for (int fm = 0; fm < 2; fm++)
                #pragma unroll
                for (int fn = 0; fn < 8; fn++)
                    hmma(acc[fm][fn], af[fm], &bf[fn >> 1][(fn & 1) * 2]);
        }
        __syncthreads();
    }

    int g = lane >> 2, tg = lane & 3;
    if (EPI == 1) {
        // routed fp16 epilogue: q | k | v | gelu(mlp)
        __half* dst;
        size_t stride;
        int cbias;
        bool is_mlp = false;
        if (n0 < HIDC)            { dst = g_qh; stride = HIDC; cbias = 0; }
        else if (n0 < 2 * HIDC)   { dst = g_kh; stride = HIDC; cbias = HIDC; }
        else if (n0 < D3H)        { dst = g_vh; stride = HIDC; cbias = 2 * HIDC; }
        else { dst = g_yh; stride = NCAT; cbias = D3H - HIDC; is_mlp = true; }
        #pragma unroll
        for (int fm = 0; fm < 2; fm++) {
            int r0 = m0 + wm * 32 + fm * 16 + g;
            int r1 = r0 + 8;
            #pragma unroll
            for (int fn = 0; fn < 8; fn++) {
                int cc = n0 + wn * 64 + fn * 8 + 2 * tg;
                float v0 = acc[fm][fn][0] + bias[cc];
                float v1 = acc[fm][fn][1] + bias[cc + 1];
                float v2 = acc[fm][fn][2] + bias[cc];
                float v3 = acc[fm][fn][3] + bias[cc + 1];
                if (is_mlp) {
                    v0 = gelu_f(v0); v1 = gelu_f(v1);
                    v2 = gelu_f(v2); v3 = gelu_f(v3);
                }
                int col = cc - cbias;
                *(__half2*)(dst + (size_t)r0 * stride + col) = __floats2half2_rn(v0, v1);
                *(__half2*)(dst + (size_t)r1 * stride + col) = __floats2half2_rn(v2, v3);
            }
        }
    } else {
        #pragma unroll
        for (int fm = 0; fm < 2; fm++) {
            int r0 = m0 + wm * 32 + fm * 16 + g;
            int r1 = r0 + 8;
            #pragma unroll
            for (int fn = 0; fn < 8; fn++) {
                int cc = n0 + wn * 64 + fn * 8 + 2 * tg;
                float v0 = acc[fm][fn][0] + bias[cc];
                float v1 = acc[fm][fn][1] + bias[cc + 1];
                float v2 = acc[fm][fn][2] + bias[cc];
                float v3 = acc[fm][fn][3] + bias[cc + 1];
                float gt0 = g_mod[2 * HIDC + cc], gt1 = g_mod[2 * HIDC + cc + 1];
                v0 = xres[(size_t)r0 * ldc + cc]     + gt0 * v0;
                v1 = xres[(size_t)r0 * ldc + cc + 1] + gt1 * v1;
                v2 = xres[(size_t)r1 * ldc + cc]     + gt0 * v2;
                v3 = xres[(size_t)r1 * ldc + cc + 1] + gt1 * v3;
                *(float2*)(Cout + (size_t)r0 * ldc + cc) = make_float2(v0, v1);
                *(float2*)(Cout + (size_t)r1 * ldc + cc) = make_float2(v2, v3);
            }
        }
    }
}

// ---------------- K5: RMSNorm(q,k) + RoPE, in-place fp16 ----------------
__global__ __launch_bounds__(128) void k_qknorm(const float* __restrict__ pe,
                                                const float* __restrict__ rqw,
                                                const float* __restrict__ rkw) {
    int l = blockIdx.x, h = blockIdx.y, d = threadIdx.x;
    size_t base = (size_t)l * HIDC + (size_t)h * 128;
    float qv = __half2float(g_qh[base + d]);
    float kv = __half2float(g_kh[base + d]);
    float q2 = qv * qv, k2 = kv * kv;
    #pragma unroll
    for (int o = 16; o; o >>= 1) {
        q2 += __shfl_xor_sync(0xffffffffu, q2, o);
        k2 += __shfl_xor_sync(0xffffffffu, k2, o);
    }
    __shared__ float sq[4], sk[4];
    int w = d >> 5, lane = d & 31;
    if (!lane) { sq[w] = q2; sk[w] = k2; }
    __syncthreads();
    float Q2 = sq[0] + sq[1] + sq[2] + sq[3];
    float K2 = sk[0] + sk[1] + sk[2] + sk[3];
    float qr = rsqrtf(Q2 * (1.f / HDC) + 1e-6f);
    float kr = rsqrtf(K2 * (1.f / HDC) + 1e-6f);
    float qn = qv * qr * rqw[d];
    float kn = kv * kr * rkw[d];
    int p = d >> 1, ii = d & 1;
    const float* rot = pe + (((size_t)l * 64 + p) * 2 + ii) * 2;
    float r0 = rot[0], r1 = rot[1];
    float qo = __shfl_xor_sync(0xffffffffu, qn, 1);
    float ko = __shfl_xor_sync(0xffffffffu, kn, 1);
    float qe = ii ? qo : qn, qod = ii ? qn : qo;
    float ke = ii ? ko : kn, kod = ii ? kn : ko;
    g_qh[base + d] = __float2half_rn(r0 * qe + r1 * qod);
    g_kh[base + d] = __float2half_rn(r0 * ke + r1 * kod);
}

// ---------------- K6: fp16 tensor-core flash attention ----------------
constexpr int AST = 136;
constexpr int OQ = 0;
constexpr int OK = 128 * AST;
constexpr int OV = OK + 64 * AST;
constexpr int ATT_H = OV + 64 * AST;
constexpr int ATT_SMEM = ATT_H * 2;            // 69632 B

__global__ __launch_bounds__(256) void k_attn() {
    extern __shared__ __half smh[];
    uint32_t sb = smem_u32(smh);

    int tid = threadIdx.x, lane = tid & 31, wid = tid >> 5;
    int g = lane >> 2, tg = lane & 3;
    int q0 = blockIdx.x * 128, h = blockIdx.y;
    size_t hb = (size_t)h * 128;
    const float scale = 0.08838834764831845f;

    // load Q tile
    for (int i = tid; i < 128 * 16; i += 256) {
        int r = i >> 4, c = (i & 15) * 8;
        *(uint4*)(smh + OQ + r * AST + c) =
            *(const uint4*)(g_qh + (size_t)(q0 + r) * HIDC + hb + c);
    }
    __syncthreads();

    // hoist Q fragments to registers (Q smem region is never rewritten)
    uint32_t qf[8][4];
    #pragma unroll
    for (int ks = 0; ks < 8; ks++) {
        int r = wid * 16 + (lane & 15);
        int kc = ks * 16 + (lane >> 4) * 8;
        ldsm4(qf[ks], sb + (uint32_t)(OQ + r * AST + kc) * 2);
    }

    float m0r = -1e30f, m1r = -1e30f, l0r = 0.f, l1r = 0.f;
    float oacc[16][4];
    #pragma unroll
    for (int i = 0; i < 16; i++)
        #pragma unroll
        for (int j = 0; j < 4; j++) oacc[i][j] = 0.f;

    for (int kb = 0; kb < LL / 64; kb++) {
        __syncthreads();
        int k0 = kb * 64;
        for (int i = tid; i < 64 * 16; i += 256) {
            int r = i >> 4, c = (i & 15) * 8;
            *(uint4*)(smh + OK + r * AST + c) =
                *(const uint4*)(g_kh + (size_t)(k0 + r) * HIDC + hb + c);
            *(uint4*)(smh + OV + r * AST + c) =
                *(const uint4*)(g_vh + (size_t)(k0 + r) * HIDC + hb + c);
        }
        __syncthreads();

        // S = Q K^T
        float sacc[8][4];
        #pragma unroll
        for (int i = 0; i < 8; i++)
            #pragma unroll
            for (int j = 0; j < 4; j++) sacc[i][j] = 0.f;
        #pragma unroll
        for (int ks = 0; ks < 8; ks++) {
            #pragma unroll
            for (int fp = 0; fp < 4; fp++) {
                uint32_t bf[4];
                int nr = fp * 16 + (lane & 7) + ((lane >> 4) & 1) * 8;
                int kc = ks * 16 + ((lane >> 3) & 1) * 8;
                ldsm4(bf, sb + (uint32_t)(OK + nr * AST + kc) * 2);
                hmma(sacc[2 * fp], qf[ks], &bf[0]);
                hmma(sacc[2 * fp + 1], qf[ks], &bf[2]);
            }
        }

        // online softmax
        float mx0 = -1e30f, mx1 = -1e30f;
        #pragma unroll
        for (int fn = 0; fn < 8; fn++) {
            sacc[fn][0] *= scale; sacc[fn][1] *= scale;
            sacc[fn][2] *= scale; sacc[fn][3] *= scale;
            mx0 = fmaxf(mx0, fmaxf(sacc[fn][0], sacc[fn][1]));
            mx1 = fmaxf(mx1, fmaxf(sacc[fn][2], sacc[fn][3]));
        }
        mx0 = fmaxf(mx0, __shfl_xor_sync(0xffffffffu, mx0, 1));
        mx0 = fmaxf(mx0, __shfl_xor_sync(0xffffffffu, mx0, 2));
        mx1 = fmaxf(mx1, __shfl_xor_sync(0xffffffffu, mx1, 1));
        mx1 = fmaxf(mx1, __shfl_xor_sync(0xffffffffu, mx1, 2));
        float mn0 = fmaxf(m0r, mx0), mn1 = fmaxf(m1r, mx1);
        float cr0 = __expf(m0r - mn0), cr1 = __expf(m1r - mn1);
        float s0 = 0.f, s1 = 0.f;
        #pragma unroll
        for (int fn = 0; fn < 8; fn++) {
            sacc[fn][0] = __expf(sacc[fn][0] - mn0);
            sacc[fn][1] = __expf(sacc[fn][1] - mn0);
            sacc[fn][2] = __expf(sacc[fn][2] - mn1);
            sacc[fn][3] = __expf(sacc[fn][3] - mn1);
            s0 += sacc[fn][0] + sacc[fn][1];
            s1 += sacc[fn][2] + sacc[fn][3];
        }
        s0 += __shfl_xor_sync(0xffffffffu, s0, 1);
        s0 += __shfl_xor_sync(0xffffffffu, s0, 2);
        s1 += __shfl_xor_sync(0xffffffffu, s1, 1);
        s1 += __shfl_xor_sync(0xffffffffu, s1, 2);
        l0r = l0r * cr0 + s0;
        l1r = l1r * cr1 + s1;
        m0r = mn0; m1r = mn1;
        #pragma unroll
        for (int fn = 0; fn < 16; fn++) {
            oacc[fn][0] *= cr0; oacc[fn][1] *= cr0;
            oacc[fn][2] *= cr1; oacc[fn][3] *= cr1;
        }

        // O += P V
        #pragma unroll
        for (int ks = 0; ks < 4; ks++) {
            uint32_t pa[4];
            pa[0] = packh2(sacc[2 * ks][0],     sacc[2 * ks][1]);
            pa[1] = packh2(sacc[2 * ks][2],     sacc[2 * ks][3]);
            pa[2] = packh2(sacc[2 * ks + 1][0], sacc[2 * ks + 1][1]);
            pa[3] = packh2(sacc[2 * ks + 1][2], sacc[2 * ks + 1][3]);
            #pragma unroll
            for (int fp = 0; fp < 8; fp++) {
                uint32_t bf[4];
                int kr = ks * 16 + (lane & 7) + ((lane >> 3) & 1) * 8;
                int dc = fp * 16 + (lane >> 4) * 8;
                ldsm4t(bf, sb + (uint32_t)(OV + kr * AST + dc) * 2);
                hmma(oacc[2 * fp], pa, &bf[0]);
                hmma(oacc[2 * fp + 1], pa, &bf[2]);
            }
        }
    }

    float inv0 = 1.f / l0r, inv1 = 1.f / l1r;
    int r0 = q0 + wid * 16 + g;
    #pragma unroll
    for (int fn = 0; fn < 16; fn++) {
        int c = (int)hb + fn * 8 + 2 * tg;
        *(__half2*)(g_yh + (size_t)r0 * NCAT + c) =
            __floats2half2_rn(oacc[fn][0] * inv0, oacc[fn][1] * inv0);
        *(__half2*)(g_yh + (size_t)(r0 + 8) * NCAT + c) =
            __floats2half2_rn(oacc[fn][2] * inv1, oacc[fn][3] * inv1);
    }
}

// ---------------- launch ----------------
extern "C" void kernel_launch(void* const* d_in, const int* in_sizes, int n_in,
                              void* d_out, int out_size) {
    const float* x     = (const float*)d_in[0];
    const float* vec   = (const float*)d_in[1];
    const float* pe    = (const float*)d_in[2];
    const float* mod_w = (const float*)d_in[3];
    const float* mod_b = (const float*)d_in[4];
    const float* w1    = (const float*)d_in[5];
    const float* b1    = (const float*)d_in[6];
    const float* ld1   = (const float*)d_in[7];
    const float* lu1   = (const float*)d_in[8];
    const float* w2    = (const float*)d_in[9];
    const float* b2    = (const float*)d_in[10];
    const float* ld2   = (const float*)d_in[11];
    const float* lu2   = (const float*)d_in[12];
    const float* rqw   = (const float*)d_in[13];
    const float* rkw   = (const float*)d_in[14];
    float* out = (float*)d_out;

    cudaFuncSetAttribute(k_attn, cudaFuncAttributeMaxDynamicSharedMemorySize, ATT_SMEM);
    cudaFuncSetAttribute((const void*)k_gemm<1, 12>, cudaFuncAttributeMaxDynamicSharedMemorySize, GEMM_SMEM);
    cudaFuncSetAttribute((const void*)k_gemm<2, 6>,  cudaFuncAttributeMaxDynamicSharedMemorySize, GEMM_SMEM);

    // convert weights to fp16
    k_half<<<(int)((size_t)NQKV * HIDC / 2048), 256>>>(w1, 0);
    k_half<<<(int)((size_t)HIDC * NCAT / 2048), 256>>>(w2, 1);
    k_half<<<NQKV * RK / 2048, 256>>>(lu1, 2);
    k_half<<<HIDC * RK / 2048, 256>>>(lu2, 3);

    k_mod<<<D3H / 8, 256>>>(vec, mod_w, mod_b);
    k_ln<<<LL, 256>>>(x);
    k_lowrank<<<LL, 256>>>(ld1, HIDC, 0);
    {
        int nblocks = (LL / 128) * (NQKV / 128);   // 36 * 168
        k_gemm<1, 12><<<nblocks, 256, GEMM_SMEM>>>(b1, nullptr, HIDC, NQKV, NQKV, nullptr);
    }
    {
        dim3 gq(LL, NHC);
        k_qknorm<<<gq, 128>>>(pe, rqw, rkw);
    }
    {
        dim3 ga(LL / 128, NHC);
        k_attn<<<ga, 256, ATT_SMEM>>>();
    }
    k_lowrank<<<LL, 256>>>(ld2, NCAT, 1);
    {
        int nblocks = (LL / 128) * (HIDC / 128);   // 36 * 24
        k_gemm<2, 6><<<nblocks, 256, GEMM_SMEM>>>(b2, out, NCAT, HIDC, HIDC, x);
    }
}

// round 7
// speedup vs baseline: 8.6497x; 1.2601x over previous
#include <cuda_runtime.h>
#include <cuda_fp16.h>
#include <math.h>
#include <stdint.h>

// ---------------- problem constants ----------------
constexpr int LL   = 4608;
constexpr int HIDC = 3072;
constexpr int NHC  = 24;
constexpr int HDC  = 128;
constexpr int MLPC = 12288;
constexpr int RK   = 32;
constexpr int D3H  = 3 * HIDC;          // 9216
constexpr int NQKV = 3 * HIDC + MLPC;   // 21504
constexpr int NCAT = HIDC + MLPC;       // 15360

// ---------------- scratch (device globals) ----------------
__device__ float  g_mod[D3H];
__device__ __half g_xmodh[(size_t)LL * HIDC];
__device__ __half g_yh[(size_t)LL * NCAT];      // attn | gelu(mlp)  (GEMM2 A)
__device__ __half g_qh[(size_t)LL * HIDC];
__device__ __half g_kh[(size_t)LL * HIDC];
__device__ __half g_vh[(size_t)LL * HIDC];
__device__ __half g_t1h[LL * RK];
__device__ __half g_t2h[LL * RK];
__device__ __half g_w1h[(size_t)NQKV * HIDC];
__device__ __half g_w2h[(size_t)HIDC * NCAT];
__device__ __half g_lu1h[NQKV * RK];
__device__ __half g_lu2h[HIDC * RK];
__device__ __half g_zeroh[8];                   // zero-initialized

// ---------------- asm helpers ----------------
__device__ __forceinline__ uint32_t smem_u32(const void* p) {
    uint32_t a;
    asm("{ .reg .u64 t; cvta.to.shared.u64 t, %1; cvt.u32.u64 %0, t; }" : "=r"(a) : "l"(p));
    return a;
}
__device__ __forceinline__ void cp16s(uint32_t s, const void* g) {
    asm volatile("cp.async.cg.shared.global [%0], [%1], 16;" :: "r"(s), "l"(g));
}
#define CP_COMMIT() asm volatile("cp.async.commit_group;")
#define CP_WAIT(N)  asm volatile("cp.async.wait_group %0;" :: "n"(N))

__device__ __forceinline__ void ldsm4(uint32_t* r, uint32_t a) {
    asm volatile("ldmatrix.sync.aligned.m8n8.x4.shared.b16 {%0,%1,%2,%3}, [%4];"
                 : "=r"(r[0]), "=r"(r[1]), "=r"(r[2]), "=r"(r[3]) : "r"(a));
}
__device__ __forceinline__ void ldsm4t(uint32_t* r, uint32_t a) {
    asm volatile("ldmatrix.sync.aligned.m8n8.x4.trans.shared.b16 {%0,%1,%2,%3}, [%4];"
                 : "=r"(r[0]), "=r"(r[1]), "=r"(r[2]), "=r"(r[3]) : "r"(a));
}
__device__ __forceinline__ void hmma(float* c, const uint32_t* a, const uint32_t* b) {
    asm volatile(
        "mma.sync.aligned.m16n8k16.row.col.f32.f16.f16.f32 "
        "{%0,%1,%2,%3}, {%4,%5,%6,%7}, {%8,%9}, {%0,%1,%2,%3};"
        : "+f"(c[0]), "+f"(c[1]), "+f"(c[2]), "+f"(c[3])
        : "r"(a[0]), "r"(a[1]), "r"(a[2]), "r"(a[3]), "r"(b[0]), "r"(b[1]));
}
__device__ __forceinline__ uint32_t packh2(float x, float y) {
    __half2 h = __floats2half2_rn(x, y);
    return *(uint32_t*)&h;
}
__device__ __forceinline__ float gelu_f(float v) {
    float u = 0.7978845608028654f * (v + 0.044715f * v * v * v);
    float t = 1.f - 2.f / (__expf(2.f * u) + 1.f);
    return 0.5f * v * (1.f + t);
}

// ---------------- K0: convert weights to fp16 ----------------
__global__ __launch_bounds__(256) void k_half(const float* __restrict__ src, int which) {
    __half* dst = which == 0 ? g_w1h : which == 1 ? g_w2h : which == 2 ? g_lu1h : g_lu2h;
    size_t i = ((size_t)blockIdx.x * 256 + threadIdx.x) * 8;
    float4 v0 = *(const float4*)(src + i);
    float4 v1 = *(const float4*)(src + i + 4);
    __half2 h[4];
    h[0] = __floats2half2_rn(v0.x, v0.y);
    h[1] = __floats2half2_rn(v0.z, v0.w);
    h[2] = __floats2half2_rn(v1.x, v1.y);
    h[3] = __floats2half2_rn(v1.z, v1.w);
    *(uint4*)(dst + i) = *(uint4*)h;
}

// ---------------- K1: mod = silu(vec) @ mod_w^T + mod_b ----------------
__global__ __launch_bounds__(256) void k_mod(const float* __restrict__ vec,
                                             const float* __restrict__ mod_w,
                                             const float* __restrict__ mod_b) {
    int j = blockIdx.x * 8 + (threadIdx.x >> 5);
    int lane = threadIdx.x & 31;
    if (j >= D3H) return;
    const float* wr = mod_w + (size_t)j * HIDC;
    float acc = 0.f;
    for (int k = lane; k < HIDC; k += 32) {
        float s = vec[k];
        acc += (s / (1.f + expf(-s))) * wr[k];
    }
    #pragma unroll
    for (int o = 16; o; o >>= 1) acc += __shfl_xor_sync(0xffffffffu, acc, o);
    if (lane == 0) g_mod[j] = acc + mod_b[j];
}

// ---------------- K2: LayerNorm + modulation -> g_xmodh (fp16) ----------------
__global__ __launch_bounds__(256) void k_ln(const float* __restrict__ x) {
    __shared__ float rs[8], rs2[8];
    int m = blockIdx.x;
    const float* row = x + (size_t)m * HIDC;
    float v[12];
    float s = 0.f, s2 = 0.f;
    #pragma unroll
    for (int i = 0; i < 12; i++) {
        v[i] = row[threadIdx.x + i * 256];
        s += v[i]; s2 += v[i] * v[i];
    }
    int lane = threadIdx.x & 31, w = threadIdx.x >> 5;
    #pragma unroll
    for (int o = 16; o; o >>= 1) {
        s  += __shfl_xor_sync(0xffffffffu, s, o);
        s2 += __shfl_xor_sync(0xffffffffu, s2, o);
    }
    if (!lane) { rs[w] = s; rs2[w] = s2; }
    __syncthreads();
    float S = 0.f, S2 = 0.f;
    #pragma unroll
    for (int i = 0; i < 8; i++) { S += rs[i]; S2 += rs2[i]; }
    float mu = S * (1.f / HIDC);
    float var = S2 * (1.f / HIDC) - mu * mu;
    float rstd = rsqrtf(var + 1e-6f);
    __half* orow = g_xmodh + (size_t)m * HIDC;
    #pragma unroll
    for (int i = 0; i < 12; i++) {
        int c = threadIdx.x + i * 256;
        float xn = (v[i] - mu) * rstd;
        orow[c] = __float2half_rn(xn * (1.f + g_mod[HIDC + c]) + g_mod[c]);
    }
}

// ---------------- K3/K8: low-rank projector t = A @ ld^T (vectorized) ----------------
__global__ __launch_bounds__(256) void k_lowrank(const float* __restrict__ ld, int K, int sel) {
    const __half* A = sel ? g_yh : g_xmodh;
    __half* t = sel ? g_t2h : g_t1h;
    int m = blockIdx.x;
    int w = threadIdx.x >> 5, lane = threadIdx.x & 31;
    const __half* a = A + (size_t)m * K;
    const float* lrow[4];
    #pragma unroll
    for (int r = 0; r < 4; r++) lrow[r] = ld + (size_t)(w * 4 + r) * K;
    float acc4[4] = {0.f, 0.f, 0.f, 0.f};
    for (int k = lane * 8; k < K; k += 256) {
        uint4 av_u = *(const uint4*)(a + k);
        const __half2* ah = (const __half2*)&av_u;
        float2 af[4];
        #pragma unroll
        for (int i = 0; i < 4; i++) af[i] = __half22float2(ah[i]);
        #pragma unroll
        for (int r = 0; r < 4; r++) {
            float4 l0 = *(const float4*)(lrow[r] + k);
            float4 l1 = *(const float4*)(lrow[r] + k + 4);
            acc4[r] += af[0].x * l0.x + af[0].y * l0.y + af[1].x * l0.z + af[1].y * l0.w
                     + af[2].x * l1.x + af[2].y * l1.y + af[3].x * l1.z + af[3].y * l1.w;
        }
    }
    #pragma unroll
    for (int o = 16; o; o >>= 1) {
        #pragma unroll
        for (int r = 0; r < 4; r++)
            acc4[r] += __shfl_xor_sync(0xffffffffu, acc4[r], o);
    }
    if (!lane) {
        __half* tp = t + m * RK + w * 4;
        #pragma unroll
        for (int r = 0; r < 4; r++) tp[r] = __float2half_rn(acc4[r]);
    }
}

// ---------------- fp16 mma GEMM: 128x128 tile, k-tile 64, 3 stages, 1 sync/tile ----------------
constexpr int HST = 72;                 // halves per smem row (64 data + 8 pad)
constexpr int TILE_H = 128 * HST;       // 9216 halves
constexpr int STAGE_H = 2 * TILE_H;     // 18432
constexpr int STG = 3;
constexpr int GEMM_SMEM = STG * STAGE_H * 2;  // 110592 B

// EPI==1: A=g_xmodh, fused epilogue -> fp16 q/k/v/gelu(mlp)
// EPI==2: A=g_yh, out = x + gate*(acc+bias) fp32
template <int EPI, int GRP>
__global__ __launch_bounds__(256, 2) void k_gemm(const float* __restrict__ bias,
                                                 float* __restrict__ Cout,
                                                 int K, int N, int ldc,
                                                 const float* __restrict__ xres) {
    extern __shared__ __half smh[];
    uint32_t sb = smem_u32(smh);
    const __half* A  = (EPI == 1) ? g_xmodh : g_yh;
    const __half* TL = (EPI == 1) ? g_t1h : g_t2h;
    const __half* W  = (EPI == 1) ? g_w1h : g_w2h;
    const __half* LU = (EPI == 1) ? g_lu1h : g_lu2h;

    const int NNB = N / 128;
    int bid = blockIdx.x;
    int group = bid / (GRP * NNB);
    int within = bid - group * (GRP * NNB);
    int mb = group * GRP + (within % GRP);
    int nb = within / GRP;
    int m0 = mb << 7, n0 = nb << 7;

    int tid = threadIdx.x, lane = tid & 31, wid = tid >> 5;
    int wm = wid >> 1, wn = wid & 1;               // 4x2 warp grid, warptile 32x64

    const int KTm = K / 64;
    const int KT = KTm + 1;                        // + low-rank tile (zero padded to 64)

    float acc[2][8][4];
    #pragma unroll
    for (int i = 0; i < 2; i++)
        #pragma unroll
        for (int j = 0; j < 8; j++)
            #pragma unroll
            for (int q = 0; q < 4; q++) acc[i][j][q] = 0.f;

    auto issue = [&](int kt) {
        int s = kt % STG;
        uint32_t base = sb + (uint32_t)s * STAGE_H * 2;
        bool mn = kt < KTm;
        #pragma unroll
        for (int j = 0; j < 8; j++) {
            int c = tid + j * 256;                 // 0..2047
            int mat = c >> 10;                     // 0: A, 1: B
            int idx = c & 1023;
            int r = idx >> 3, ch = idx & 7;        // row 0..127, 16B chunk 0..7
            uint32_t dst = base + (uint32_t)(mat * TILE_H + r * HST + ch * 8) * 2;
            const __half* src;
            if (mn) {
                src = mat ? W + (size_t)(n0 + r) * K + kt * 64 + ch * 8
                          : A + (size_t)(m0 + r) * K + kt * 64 + ch * 8;
            } else {
                if (ch < 4)
                    src = mat ? LU + (size_t)(n0 + r) * RK + ch * 8
                              : TL + (size_t)(m0 + r) * RK + ch * 8;
                else
                    src = g_zeroh;
            }
            cp16s(dst, src);
        }
    };

    issue(0); CP_COMMIT();
    issue(1); CP_COMMIT();

    for (int kt = 0; kt < KT; kt++) {
        CP_WAIT(1);
        __syncthreads();
        if (kt + 2 < KT) issue(kt + 2);
        CP_COMMIT();
        uint32_t sA = sb + (uint32_t)(kt % STG) * STAGE_H * 2;
        uint32_t sB = sA + TILE_H * 2;
        #pragma unroll
        for (int ks = 0; ks < 4; ks++) {
            uint32_t af[2][4];
            #pragma unroll
            for (int fm = 0; fm < 2; fm++) {
                int r = wm * 32 + fm * 16 + (lane & 15);
                int kc = ks * 16 + (lane >> 4) * 8;
                ldsm4(af[fm], sA + (uint32_t)(r * HST + kc) * 2);
            }
            uint32_t bf[4][4];
            #pragma unroll
            for (int fp = 0; fp < 4; fp++) {
                int nr = wn * 64 + fp * 16 + (lane & 7) + ((lane >> 4) & 1) * 8;
                int kc = ks * 16 + ((lane >> 3) & 1) * 8;
                ldsm4(bf[fp], sB + (uint32_t)(nr * HST + kc) * 2);
            }
            #pragma unroll
            for (int fm = 0; fm < 2; fm++)
                #pragma unroll
                for (int fn = 0; fn < 8; fn++)
                    hmma(acc[fm][fn], af[fm], &bf[fn >> 1][(fn & 1) * 2]);
        }
    }

    int g = lane >> 2, tg = lane & 3;
    if (EPI == 1) {
        __half* dst;
        size_t stride;
        int cbias;
        bool is_mlp = false;
        if (n0 < HIDC)            { dst = g_qh; stride = HIDC; cbias = 0; }
        else if (n0 < 2 * HIDC)   { dst = g_kh; stride = HIDC; cbias = HIDC; }
        else if (n0 < D3H)        { dst = g_vh; stride = HIDC; cbias = 2 * HIDC; }
        else { dst = g_yh; stride = NCAT; cbias = D3H - HIDC; is_mlp = true; }
        #pragma unroll
        for (int fm = 0; fm < 2; fm++) {
            int r0 = m0 + wm * 32 + fm * 16 + g;
            int r1 = r0 + 8;
            #pragma unroll
            for (int fn = 0; fn < 8; fn++) {
                int cc = n0 + wn * 64 + fn * 8 + 2 * tg;
                float v0 = acc[fm][fn][0] + bias[cc];
                float v1 = acc[fm][fn][1] + bias[cc + 1];
                float v2 = acc[fm][fn][2] + bias[cc];
                float v3 = acc[fm][fn][3] + bias[cc + 1];
                if (is_mlp) {
                    v0 = gelu_f(v0); v1 = gelu_f(v1);
                    v2 = gelu_f(v2); v3 = gelu_f(v3);
                }
                int col = cc - cbias;
                *(__half2*)(dst + (size_t)r0 * stride + col) = __floats2half2_rn(v0, v1);
                *(__half2*)(dst + (size_t)r1 * stride + col) = __floats2half2_rn(v2, v3);
            }
        }
    } else {
        #pragma unroll
        for (int fm = 0; fm < 2; fm++) {
            int r0 = m0 + wm * 32 + fm * 16 + g;
            int r1 = r0 + 8;
            #pragma unroll
            for (int fn = 0; fn < 8; fn++) {
                int cc = n0 + wn * 64 + fn * 8 + 2 * tg;
                float v0 = acc[fm][fn][0] + bias[cc];
                float v1 = acc[fm][fn][1] + bias[cc + 1];
                float v2 = acc[fm][fn][2] + bias[cc];
                float v3 = acc[fm][fn][3] + bias[cc + 1];
                float gt0 = g_mod[2 * HIDC + cc], gt1 = g_mod[2 * HIDC + cc + 1];
                v0 = xres[(size_t)r0 * ldc + cc]     + gt0 * v0;
                v1 = xres[(size_t)r0 * ldc + cc + 1] + gt1 * v1;
                v2 = xres[(size_t)r1 * ldc + cc]     + gt0 * v2;
                v3 = xres[(size_t)r1 * ldc + cc + 1] + gt1 * v3;
                *(float2*)(Cout + (size_t)r0 * ldc + cc) = make_float2(v0, v1);
                *(float2*)(Cout + (size_t)r1 * ldc + cc) = make_float2(v2, v3);
            }
        }
    }
}

// ---------------- K5: RMSNorm(q,k) + RoPE, in-place fp16 ----------------
__global__ __launch_bounds__(128) void k_qknorm(const float* __restrict__ pe,
                                                const float* __restrict__ rqw,
                                                const float* __restrict__ rkw) {
    int l = blockIdx.x, h = blockIdx.y, d = threadIdx.x;
    size_t base = (size_t)l * HIDC + (size_t)h * 128;
    float qv = __half2float(g_qh[base + d]);
    float kv = __half2float(g_kh[base + d]);
    float q2 = qv * qv, k2 = kv * kv;
    #pragma unroll
    for (int o = 16; o; o >>= 1) {
        q2 += __shfl_xor_sync(0xffffffffu, q2, o);
        k2 += __shfl_xor_sync(0xffffffffu, k2, o);
    }
    __shared__ float sq[4], sk[4];
    int w = d >> 5, lane = d & 31;
    if (!lane) { sq[w] = q2; sk[w] = k2; }
    __syncthreads();
    float Q2 = sq[0] + sq[1] + sq[2] + sq[3];
    float K2 = sk[0] + sk[1] + sk[2] + sk[3];
    float qr = rsqrtf(Q2 * (1.f / HDC) + 1e-6f);
    float kr = rsqrtf(K2 * (1.f / HDC) + 1e-6f);
    float qn = qv * qr * rqw[d];
    float kn = kv * kr * rkw[d];
    int p = d >> 1, ii = d & 1;
    const float* rot = pe + (((size_t)l * 64 + p) * 2 + ii) * 2;
    float r0 = rot[0], r1 = rot[1];
    float qo = __shfl_xor_sync(0xffffffffu, qn, 1);
    float ko = __shfl_xor_sync(0xffffffffu, kn, 1);
    float qe = ii ? qo : qn, qod = ii ? qn : qo;
    float ke = ii ? ko : kn, kod = ii ? kn : ko;
    g_qh[base + d] = __float2half_rn(r0 * qe + r1 * qod);
    g_kh[base + d] = __float2half_rn(r0 * ke + r1 * kod);
}

// ---------------- K6: fp16 flash attention, cp.async double-buffered K/V ----------------
constexpr int AST = 136;                        // halves per smem row
constexpr int OQ = 0;
constexpr int OS = 128 * AST;                   // stages base (after Q)
constexpr int STAGE_ATT = 128 * AST;            // per stage: K 64 rows + V 64 rows
constexpr int ATT_H = OS + 2 * STAGE_ATT;       // 52224 halves
constexpr int ATT_SMEM = ATT_H * 2;             // 104448 B

__global__ __launch_bounds__(256) void k_attn() {
    extern __shared__ __half smh[];
    uint32_t sb = smem_u32(smh);

    int tid = threadIdx.x, lane = tid & 31, wid = tid >> 5;
    int g = lane >> 2, tg = lane & 3;
    int q0 = blockIdx.x * 128, h = blockIdx.y;
    size_t hb = (size_t)h * 128;
    const float scale = 0.08838834764831845f;
    const int NKB = LL / 64;

    // load Q tile (plain loads, once)
    for (int i = tid; i < 128 * 16; i += 256) {
        int r = i >> 4, c = (i & 15) * 8;
        *(uint4*)(smh + OQ + r * AST + c) =
            *(const uint4*)(g_qh + (size_t)(q0 + r) * HIDC + hb + c);
    }

    auto issueKV = [&](int kb) {
        uint32_t base = sb + (uint32_t)(OS + (kb & 1) * STAGE_ATT) * 2;
        int k0 = kb * 64;
        #pragma unroll
        for (int j = 0; j < 8; j++) {
            int c = tid + j * 256;                 // 0..2047
            int mat = c >> 10;                     // 0: K, 1: V
            int idx = c & 1023;
            int r = idx >> 4, ch = idx & 15;
            const __half* src = (mat ? g_vh : g_kh) + (size_t)(k0 + r) * HIDC + hb + ch * 8;
            uint32_t dst = base + (uint32_t)((mat * 64 + r) * AST + ch * 8) * 2;
            cp16s(dst, src);
        }
    };

    issueKV(0); CP_COMMIT();
    __syncthreads();

    // hoist Q fragments to registers
    uint32_t qf[8][4];
    #pragma unroll
    for (int ks = 0; ks < 8; ks++) {
        int r = wid * 16 + (lane & 15);
        int kc = ks * 16 + (lane >> 4) * 8;
        ldsm4(qf[ks], sb + (uint32_t)(OQ + r * AST + kc) * 2);
    }

    float m0r = -1e30f, m1r = -1e30f, l0r = 0.f, l1r = 0.f;
    float oacc[16][4];
    #pragma unroll
    for (int i = 0; i < 16; i++)
        #pragma unroll
        for (int j = 0; j < 4; j++) oacc[i][j] = 0.f;

    for (int kb = 0; kb < NKB; kb++) {
        CP_WAIT(0);
        __syncthreads();
        if (kb + 1 < NKB) { issueKV(kb + 1); CP_COMMIT(); }
        uint32_t sK = sb + (uint32_t)(OS + (kb & 1) * STAGE_ATT) * 2;
        uint32_t sV = sK + (uint32_t)(64 * AST) * 2;

        // S = Q K^T
        float sacc[8][4];
        #pragma unroll
        for (int i = 0; i < 8; i++)
            #pragma unroll
            for (int j = 0; j < 4; j++) sacc[i][j] = 0.f;
        #pragma unroll
        for (int ks = 0; ks < 8; ks++) {
            #pragma unroll
            for (int fp = 0; fp < 4; fp++) {
                uint32_t bf[4];
                int nr = fp * 16 + (lane & 7) + ((lane >> 4) & 1) * 8;
                int kc = ks * 16 + ((lane >> 3) & 1) * 8;
                ldsm4(bf, sK + (uint32_t)(nr * AST + kc) * 2);
                hmma(sacc[2 * fp], qf[ks], &bf[0]);
                hmma(sacc[2 * fp + 1], qf[ks], &bf[2]);
            }
        }

        // online softmax
        float mx0 = -1e30f, mx1 = -1e30f;
        #pragma unroll
        for (int fn = 0; fn < 8; fn++) {
            sacc[fn][0] *= scale; sacc[fn][1] *= scale;
            sacc[fn][2] *= scale; sacc[fn][3] *= scale;
            mx0 = fmaxf(mx0, fmaxf(sacc[fn][0], sacc[fn][1]));
            mx1 = fmaxf(mx1, fmaxf(sacc[fn][2], sacc[fn][3]));
        }
        mx0 = fmaxf(mx0, __shfl_xor_sync(0xffffffffu, mx0, 1));
        mx0 = fmaxf(mx0, __shfl_xor_sync(0xffffffffu, mx0, 2));
        mx1 = fmaxf(mx1, __shfl_xor_sync(0xffffffffu, mx1, 1));
        mx1 = fmaxf(mx1, __shfl_xor_sync(0xffffffffu, mx1, 2));
        float mn0 = fmaxf(m0r, mx0), mn1 = fmaxf(m1r, mx1);
        float cr0 = __expf(m0r - mn0), cr1 = __expf(m1r - mn1);
        float s0 = 0.f, s1 = 0.f;
        #pragma unroll
        for (int fn = 0; fn < 8; fn++) {
            sacc[fn][0] = __expf(sacc[fn][0] - mn0);
            sacc[fn][1] = __expf(sacc[fn][1] - mn0);
            sacc[fn][2] = __expf(sacc[fn][2] - mn1);
            sacc[fn][3] = __expf(sacc[fn][3] - mn1);
            s0 += sacc[fn][0] + sacc[fn][1];
            s1 += sacc[fn][2] + sacc[fn][3];
        }
        s0 += __shfl_xor_sync(0xffffffffu, s0, 1);
        s0 += __shfl_xor_sync(0xffffffffu, s0, 2);
        s1 += __shfl_xor_sync(0xffffffffu, s1, 1);
        s1 += __shfl_xor_sync(0xffffffffu, s1, 2);
        l0r = l0r * cr0 + s0;
        l1r = l1r * cr1 + s1;
        m0r = mn0; m1r = mn1;
        #pragma unroll
        for (int fn = 0; fn < 16; fn++) {
            oacc[fn][0] *= cr0; oacc[fn][1] *= cr0;
            oacc[fn][2] *= cr1; oacc[fn][3] *= cr1;
        }

        // O += P V
        #pragma unroll
        for (int ks = 0; ks < 4; ks++) {
            uint32_t pa[4];
            pa[0] = packh2(sacc[2 * ks][0],     sacc[2 * ks][1]);
            pa[1] = packh2(sacc[2 * ks][2],     sacc[2 * ks][3]);
            pa[2] = packh2(sacc[2 * ks + 1][0], sacc[2 * ks + 1][1]);
            pa[3] = packh2(sacc[2 * ks + 1][2], sacc[2 * ks + 1][3]);
            #pragma unroll
            for (int fp = 0; fp < 8; fp++) {
                uint32_t bf[4];
                int kr = ks * 16 + (lane & 7) + ((lane >> 3) & 1) * 8;
                int dc = fp * 16 + (lane >> 4) * 8;
                ldsm4t(bf, sV + (uint32_t)(kr * AST + dc) * 2);
                hmma(oacc[2 * fp], pa, &bf[0]);
                hmma(oacc[2 * fp + 1], pa, &bf[2]);
            }
        }
    }

    float inv0 = 1.f / l0r, inv1 = 1.f / l1r;
    int r0 = q0 + wid * 16 + g;
    #pragma unroll
    for (int fn = 0; fn < 16; fn++) {
        int c = (int)hb + fn * 8 + 2 * tg;
        *(__half2*)(g_yh + (size_t)r0 * NCAT + c) =
            __floats2half2_rn(oacc[fn][0] * inv0, oacc[fn][1] * inv0);
        *(__half2*)(g_yh + (size_t)(r0 + 8) * NCAT + c) =
            __floats2half2_rn(oacc[fn][2] * inv1, oacc[fn][3] * inv1);
    }
}

// ---------------- launch ----------------
extern "C" void kernel_launch(void* const* d_in, const int* in_sizes, int n_in,
                              void* d_out, int out_size) {
    const float* x     = (const float*)d_in[0];
    const float* vec   = (const float*)d_in[1];
    const float* pe    = (const float*)d_in[2];
    const float* mod_w = (const float*)d_in[3];
    const float* mod_b = (const float*)d_in[4];
    const float* w1    = (const float*)d_in[5];
    const float* b1    = (const float*)d_in[6];
    const float* ld1   = (const float*)d_in[7];
    const float* lu1   = (const float*)d_in[8];
    const float* w2    = (const float*)d_in[9];
    const float* b2    = (const float*)d_in[10];
    const float* ld2   = (const float*)d_in[11];
    const float* lu2   = (const float*)d_in[12];
    const float* rqw   = (const float*)d_in[13];
    const float* rkw   = (const float*)d_in[14];
    float* out = (float*)d_out;

    cudaFuncSetAttribute(k_attn, cudaFuncAttributeMaxDynamicSharedMemorySize, ATT_SMEM);
    cudaFuncSetAttribute((const void*)k_gemm<1, 36>, cudaFuncAttributeMaxDynamicSharedMemorySize, GEMM_SMEM);
    cudaFuncSetAttribute((const void*)k_gemm<2, 18>, cudaFuncAttributeMaxDynamicSharedMemorySize, GEMM_SMEM);

    // convert weights to fp16
    k_half<<<(int)((size_t)NQKV * HIDC / 2048), 256>>>(w1, 0);
    k_half<<<(int)((size_t)HIDC * NCAT / 2048), 256>>>(w2, 1);
    k_half<<<NQKV * RK / 2048, 256>>>(lu1, 2);
    k_half<<<HIDC * RK / 2048, 256>>>(lu2, 3);

    k_mod<<<D3H / 8, 256>>>(vec, mod_w, mod_b);
    k_ln<<<LL, 256>>>(x);
    k_lowrank<<<LL, 256>>>(ld1, HIDC, 0);
    {
        int nblocks = (LL / 128) * (NQKV / 128);   // 36 * 168
        k_gemm<1, 36><<<nblocks, 256, GEMM_SMEM>>>(b1, nullptr, HIDC, NQKV, NQKV, nullptr);
    }
    {
        dim3 gq(LL, NHC);
        k_qknorm<<<gq, 128>>>(pe, rqw, rkw);
    }
    {
        dim3 ga(LL / 128, NHC);
        k_attn<<<ga, 256, ATT_SMEM>>>();
    }
    k_lowrank<<<LL, 256>>>(ld2, NCAT, 1);
    {
        int nblocks = (LL / 128) * (HIDC / 128);   // 36 * 24
        k_gemm<2, 18><<<nblocks, 256, GEMM_SMEM>>>(b2, out, NCAT, HIDC, HIDC, x);
    }
}